// round 2
// baseline (speedup 1.0000x reference)
#include <cuda_runtime.h>
#include <math.h>
#include <stdint.h>
#include <stddef.h>

#define BATCH_N 65536
#define QDIM    256
#define BM 128
#define BN 128
#define BK 16

// ---------------- scratch (allocation-free: __device__ globals) ----------------
static __device__ float g_h[(size_t)BATCH_N * 768];          // wide hidden (768/512) + nl temp
static __device__ float g_bufs[3][(size_t)BATCH_N * QDIM];   // rotating 256-wide activation buffers
static __device__ float g_tent[8 * QDIM * QDIM];             // tanh(ent[li])
static __device__ float g_gate[4][8 * QDIM];                 // lin, p3, p4, p5

struct EpiParams {
    const float* bias;
    const float* cmat;    // elementwise companion matrix (cur / cur2), ld = ldc
    const float* resmat;  // residual matrix, ld = ldc
    const float* lin;     // per-column gate params (256)
    const float* p3;
    const float* p4;
    const float* p5;
    float alpha;
    int   blend;
};

enum { E_BIAS = 0, E_SILU = 1, E_TANH = 2, E_GATE = 3, E_NL = 4 };

// ---------------- templated SGEMM: C[M,N] = A[M,K] @ B[K,N] (+ epilogue) -------
template <int EPI>
__global__ void __launch_bounds__(256, 2) sgemm_k(
    const float* __restrict__ A, int lda,
    const float* __restrict__ B, int ldb,
    float* __restrict__ C, int ldc,
    int K, EpiParams ep)
{
    __shared__ __align__(16) float As[BK][BM + 4];  // [k][m], padded vs STS conflicts
    __shared__ __align__(16) float Bs[BK][BN];      // [k][n]

    const int tid = threadIdx.x;
    const int tx  = tid & 15;
    const int ty  = tid >> 4;
    const int m0  = blockIdx.y * BM;
    const int n0  = blockIdx.x * BN;

    // global->smem load mapping: 2 float4 per thread for A tile (128x16) and B tile (16x128)
    const int g0 = tid, g1 = tid + 256;
    const int ar0 = g0 >> 2, ac0 = (g0 & 3) * 4;
    const int ar1 = g1 >> 2, ac1 = (g1 & 3) * 4;
    const int br0 = g0 >> 5, bc0 = (g0 & 31) * 4;
    const int br1 = g1 >> 5, bc1 = (g1 & 31) * 4;

    const float* pa0 = A + (size_t)(m0 + ar0) * lda + ac0;
    const float* pa1 = A + (size_t)(m0 + ar1) * lda + ac1;
    const float* pb0 = B + (size_t)br0 * ldb + n0 + bc0;
    const float* pb1 = B + (size_t)br1 * ldb + n0 + bc1;

    float acc[8][8];
#pragma unroll
    for (int i = 0; i < 8; i++)
#pragma unroll
        for (int j = 0; j < 8; j++) acc[i][j] = 0.0f;

    float4 ra0 = *(const float4*)pa0;
    float4 ra1 = *(const float4*)pa1;
    float4 rb0 = *(const float4*)pb0;
    float4 rb1 = *(const float4*)pb1;

    const int ktiles = K / BK;
    for (int kt = 0; kt < ktiles; kt++) {
        As[ac0 + 0][ar0] = ra0.x; As[ac0 + 1][ar0] = ra0.y;
        As[ac0 + 2][ar0] = ra0.z; As[ac0 + 3][ar0] = ra0.w;
        As[ac1 + 0][ar1] = ra1.x; As[ac1 + 1][ar1] = ra1.y;
        As[ac1 + 2][ar1] = ra1.z; As[ac1 + 3][ar1] = ra1.w;
        *(float4*)&Bs[br0][bc0] = rb0;
        *(float4*)&Bs[br1][bc1] = rb1;
        __syncthreads();

        pa0 += BK; pa1 += BK;
        pb0 += (size_t)BK * ldb; pb1 += (size_t)BK * ldb;
        if (kt + 1 < ktiles) {  // prefetch next tile while computing this one
            ra0 = *(const float4*)pa0; ra1 = *(const float4*)pa1;
            rb0 = *(const float4*)pb0; rb1 = *(const float4*)pb1;
        }

#pragma unroll
        for (int k = 0; k < BK; k++) {
            float a[8], b[8];
            *(float4*)&a[0] = *(const float4*)&As[k][ty * 8];
            *(float4*)&a[4] = *(const float4*)&As[k][ty * 8 + 4];
            *(float4*)&b[0] = *(const float4*)&Bs[k][tx * 8];
            *(float4*)&b[4] = *(const float4*)&Bs[k][tx * 8 + 4];
#pragma unroll
            for (int i = 0; i < 8; i++)
#pragma unroll
                for (int j = 0; j < 8; j++) acc[i][j] += a[i] * b[j];
        }
        __syncthreads();
    }

    // -------- epilogue --------
    const int nb = n0 + tx * 8;
    float bias8[8], lin8[8], p38[8], p48[8], p58[8];
    if (EPI != E_GATE) {
#pragma unroll
        for (int j = 0; j < 8; j++) bias8[j] = ep.bias[nb + j];
    }
    if (EPI == E_GATE) {
#pragma unroll
        for (int j = 0; j < 8; j++) {
            lin8[j] = ep.lin[nb + j];
            p38[j]  = ep.p3[nb + j];
            p48[j]  = ep.p4[nb + j];
            p58[j]  = ep.p5[nb + j];
        }
    }

#pragma unroll
    for (int i = 0; i < 8; i++) {
        const int m = m0 + ty * 8 + i;
        const size_t rowo = (size_t)m * ldc + nb;
        float out8[8];
#pragma unroll
        for (int j = 0; j < 8; j++) {
            float v = acc[i][j];
            if (EPI == E_BIAS) {
                v += bias8[j];
            } else if (EPI == E_SILU) {
                v += bias8[j];
                v = v / (1.0f + expf(-v));
            } else if (EPI == E_TANH) {
                v += bias8[j];
                v = tanhf(v);
            } else if (EPI == E_GATE) {
                const float c = ep.cmat[rowo + j];
                const float g = (lin8[j] * c
                                 + 0.5f * sinf(p38[j] * c + p48[j])
                                 + 0.5f * cosf(p58[j] * c)) * 0.25f;
                v = (c + 0.3f * g + 0.2f * v) * (1.0f / 1.5f);
                if (ep.blend)
                    v = ep.alpha * v + (1.0f - ep.alpha) * ep.resmat[rowo + j];
            } else if (EPI == E_NL) {
                v += bias8[j];
                const float c2 = ep.cmat[rowo + j];
                v = ep.alpha * (c2 + 0.1f * v) + (1.0f - ep.alpha) * ep.resmat[rowo + j];
            }
            out8[j] = v;
        }
        *(float4*)&C[rowo]     = make_float4(out8[0], out8[1], out8[2], out8[3]);
        *(float4*)&C[rowo + 4] = make_float4(out8[4], out8[5], out8[6], out8[7]);
    }
}

// ---------------- LayerNorm (over 768) + exact gelu, in place -------------------
__global__ void ln_gelu_k(float* __restrict__ h,
                          const float* __restrict__ w,
                          const float* __restrict__ b)
{
    const int row = blockIdx.x;
    float* hr = h + (size_t)row * 768;
    const int t = threadIdx.x;

    const float v0 = hr[t], v1 = hr[t + 256], v2 = hr[t + 512];
    float s  = v0 + v1 + v2;
    float ss = v0 * v0 + v1 * v1 + v2 * v2;

#pragma unroll
    for (int o = 16; o > 0; o >>= 1) {
        s  += __shfl_down_sync(0xffffffffu, s, o);
        ss += __shfl_down_sync(0xffffffffu, ss, o);
    }
    __shared__ float rs[8], rss[8];
    __shared__ float mu_s, rstd_s;
    const int lane = t & 31, wp = t >> 5;
    if (lane == 0) { rs[wp] = s; rss[wp] = ss; }
    __syncthreads();
    if (t == 0) {
        float S = 0.0f, SS = 0.0f;
#pragma unroll
        for (int k = 0; k < 8; k++) { S += rs[k]; SS += rss[k]; }
        const float mu  = S * (1.0f / 768.0f);
        const float var = SS * (1.0f / 768.0f) - mu * mu;
        mu_s = mu;
        rstd_s = rsqrtf(var + 1e-5f);
    }
    __syncthreads();
    const float mu = mu_s, rstd = rstd_s;

#pragma unroll
    for (int k = 0; k < 3; k++) {
        const int c = t + k * 256;
        float x = (((k == 0) ? v0 : (k == 1) ? v1 : v2) - mu) * rstd * w[c] + b[c];
        hr[c] = 0.5f * x * (1.0f + erff(x * 0.70710678118654752f));
    }
}

// ---------------- row L2-normalize (256) + tanh -------------------------------
__global__ void norm_tanh_k(const float* __restrict__ in, float* __restrict__ out)
{
    const int wp = threadIdx.x >> 5, lane = threadIdx.x & 31;
    const size_t row = (size_t)blockIdx.x * 8 + wp;
    const float* r = in + row * QDIM;
    const float4 a = *(const float4*)(r + lane * 4);
    const float4 c = *(const float4*)(r + 128 + lane * 4);
    float s = a.x * a.x + a.y * a.y + a.z * a.z + a.w * a.w
            + c.x * c.x + c.y * c.y + c.z * c.z + c.w * c.w;
#pragma unroll
    for (int o = 16; o > 0; o >>= 1) s += __shfl_xor_sync(0xffffffffu, s, o);
    const float inv = 1.0f / (sqrtf(s) + 1e-8f);
    float* o = out + row * QDIM;
    *(float4*)(o + lane * 4) =
        make_float4(tanhf(a.x * inv), tanhf(a.y * inv), tanhf(a.z * inv), tanhf(a.w * inv));
    *(float4*)(o + 128 + lane * 4) =
        make_float4(tanhf(c.x * inv), tanhf(c.y * inv), tanhf(c.z * inv), tanhf(c.w * inv));
}

// ---------------- prep: tanh(ent), gate param folding -------------------------
__global__ void prep_k(const float* __restrict__ ent, const float* __restrict__ gp,
                       float* __restrict__ tent, float* __restrict__ lin,
                       float* __restrict__ p3, float* __restrict__ p4,
                       float* __restrict__ p5)
{
    const int i = blockIdx.x * blockDim.x + threadIdx.x;
    if (i < 8 * QDIM * QDIM) tent[i] = tanhf(ent[i]);
    if (i < 8 * QDIM) {
        const float* p = gp + (size_t)i * 6;
        lin[i] = sinf(p[0]) + cosf(p[1]) + tanhf(p[2]);
        p3[i] = p[3]; p4[i] = p[4]; p5[i] = p[5];
    }
}

// ---------------- host orchestration ------------------------------------------
static void launch_gemm(int epi, const float* A, int lda, const float* B, int ldb,
                        float* C, int ldc, int K, int N, const EpiParams& ep)
{
    dim3 grid(N / BN, BATCH_N / BM);
    dim3 blk(256);
    switch (epi) {
        case E_BIAS: sgemm_k<E_BIAS><<<grid, blk>>>(A, lda, B, ldb, C, ldc, K, ep); break;
        case E_SILU: sgemm_k<E_SILU><<<grid, blk>>>(A, lda, B, ldb, C, ldc, K, ep); break;
        case E_TANH: sgemm_k<E_TANH><<<grid, blk>>>(A, lda, B, ldb, C, ldc, K, ep); break;
        case E_GATE: sgemm_k<E_GATE><<<grid, blk>>>(A, lda, B, ldb, C, ldc, K, ep); break;
        case E_NL:   sgemm_k<E_NL>  <<<grid, blk>>>(A, lda, B, ldb, C, ldc, K, ep); break;
    }
}

extern "C" void kernel_launch(void* const* d_in, const int* in_sizes, int n_in,
                              void* d_out, int out_size)
{
    (void)in_sizes; (void)n_in; (void)out_size;
    const float* x    = (const float*)d_in[0];
    const float* w01  = (const float*)d_in[1];
    const float* b01  = (const float*)d_in[2];
    const float* lnw  = (const float*)d_in[3];
    const float* lnb  = (const float*)d_in[4];
    const float* w02  = (const float*)d_in[5];
    const float* b02  = (const float*)d_in[6];
    const float* w11  = (const float*)d_in[7];
    const float* b11  = (const float*)d_in[8];
    const float* w12  = (const float*)d_in[9];
    const float* b12  = (const float*)d_in[10];
    const float* wqkv = (const float*)d_in[11];
    const float* bqkv = (const float*)d_in[12];
    const float* wo   = (const float*)d_in[13];
    const float* bo   = (const float*)d_in[14];
    const float* gp   = (const float*)d_in[15];
    const float* ent  = (const float*)d_in[16];
    const float* nw1  = (const float*)d_in[17];
    const float* nb1  = (const float*)d_in[18];
    const float* nw2  = (const float*)d_in[19];
    const float* nb2  = (const float*)d_in[20];

    float *H, *BUFB, *TENT, *GATEB;
    cudaGetSymbolAddress((void**)&H,     g_h);
    cudaGetSymbolAddress((void**)&BUFB,  g_bufs);
    cudaGetSymbolAddress((void**)&TENT,  g_tent);
    cudaGetSymbolAddress((void**)&GATEB, g_gate);
    float* BUF[3];
    for (int k = 0; k < 3; k++) BUF[k] = BUFB + (size_t)k * BATCH_N * QDIM;
    float* LIN = GATEB + 0 * 8 * QDIM;
    float* P3  = GATEB + 1 * 8 * QDIM;
    float* P4  = GATEB + 2 * 8 * QDIM;
    float* P5  = GATEB + 3 * 8 * QDIM;

    prep_k<<<(8 * QDIM * QDIM + 255) / 256, 256>>>(ent, gp, TENT, LIN, P3, P4, P5);

    float* cur = (float*)x;
    for (int li = 0; li < 8; li++) {
        // pick the two rotating buffers not currently holding `cur` (the residual)
        float* s[2]; int cnt = 0;
        for (int k = 0; k < 3; k++)
            if (BUF[k] != cur && cnt < 2) s[cnt++] = BUF[k];

        const int t = li % 3;
        float *mid, *c2;
        EpiParams e0 = {};
        if (t == 0) {
            const int i = li / 3;
            e0.bias = b01 + i * 768;
            launch_gemm(E_BIAS, cur, QDIM, w01 + (size_t)i * QDIM * 768, 768, H, 768, QDIM, 768, e0);
            ln_gelu_k<<<BATCH_N, 256>>>(H, lnw + i * 768, lnb + i * 768);
            e0.bias = b02 + i * QDIM;
            launch_gemm(E_BIAS, H, 768, w02 + (size_t)i * 768 * QDIM, QDIM, s[0], QDIM, 768, QDIM, e0);
            mid = s[0]; c2 = s[1];
        } else if (t == 1) {
            const int i = (li - 1) / 3;
            e0.bias = b11 + i * 512;
            launch_gemm(E_SILU, cur, QDIM, w11 + (size_t)i * QDIM * 512, 512, H, 512, QDIM, 512, e0);
            e0.bias = b12 + i * QDIM;
            launch_gemm(E_BIAS, H, 512, w12 + (size_t)i * 512 * QDIM, QDIM, s[0], QDIM, 512, QDIM, e0);
            mid = s[0]; c2 = s[1];
        } else {
            const int i = (li - 2) / 3;
            // only the V slice of qkv matters: columns [512, 768)
            e0.bias = bqkv + i * 768 + 512;
            launch_gemm(E_BIAS, cur, QDIM, wqkv + (size_t)i * QDIM * 768 + 512, 768, s[0], QDIM, QDIM, QDIM, e0);
            e0.bias = bo + i * QDIM;
            launch_gemm(E_BIAS, s[0], QDIM, wo + (size_t)i * QDIM * QDIM, QDIM, s[1], QDIM, QDIM, QDIM, e0);
            mid = s[1]; c2 = s[0];  // v (s[0]) is dead after this; reuse for c2
        }

        const int odd = li & 1;
        const float alpha = (li < 4) ? 0.8f : 0.6f;

        // entangled = mid @ tanh(ent[li]); epilogue fuses gate + combine (+ alpha blend on even layers)
        EpiParams eg = {};
        eg.cmat = mid; eg.resmat = cur;
        eg.lin = LIN + li * QDIM; eg.p3 = P3 + li * QDIM;
        eg.p4 = P4 + li * QDIM;   eg.p5 = P5 + li * QDIM;
        eg.alpha = alpha; eg.blend = !odd;
        launch_gemm(E_GATE, mid, QDIM, TENT + (size_t)li * QDIM * QDIM, QDIM, c2, QDIM, QDIM, QDIM, eg);

        if (odd) {
            const int j = li / 2;
            EpiParams et = {}; et.bias = nb1 + j * QDIM;
            launch_gemm(E_TANH, c2, QDIM, nw1 + (size_t)j * QDIM * QDIM, QDIM, H, QDIM, QDIM, QDIM, et);
            EpiParams en = {}; en.bias = nb2 + j * QDIM;
            en.cmat = c2; en.resmat = cur; en.alpha = alpha;
            launch_gemm(E_NL, H, QDIM, nw2 + (size_t)j * QDIM * QDIM, QDIM, c2, QDIM, QDIM, QDIM, en);
        }

        float* dst = (li == 7) ? (float*)d_out : c2;
        norm_tanh_k<<<BATCH_N / 8, 256>>>(c2, dst);
        cur = dst;
    }
}

// round 4
// speedup vs baseline: 1.7069x; 1.7069x over previous
#include <cuda_runtime.h>
#include <cuda_bf16.h>
#include <math.h>
#include <stdint.h>
#include <stddef.h>

#define BATCH_N 65536
#define QD      256

// ---------------- ptx helpers ---------------------------------------------------
__device__ __forceinline__ uint32_t smem_u32(const void* p) {
    uint32_t a;
    asm("{ .reg .u64 t; cvta.to.shared.u64 t, %1; cvt.u32.u64 %0, t; }" : "=r"(a) : "l"(p));
    return a;
}

#define CP_ASYNC16(dst, src) \
    asm volatile("cp.async.cg.shared.global [%0], [%1], 16;" :: "r"(dst), "l"(src) : "memory")
#define CP_COMMIT() asm volatile("cp.async.commit_group;" ::: "memory")
#define CP_WAIT1()  asm volatile("cp.async.wait_group 1;" ::: "memory")

#define LDSM_X4(r, addr) \
    asm volatile("ldmatrix.sync.aligned.m8n8.x4.shared.b16 {%0,%1,%2,%3}, [%4];" \
        : "=r"((r)[0]), "=r"((r)[1]), "=r"((r)[2]), "=r"((r)[3]) : "r"(addr))

#define MMA_BF16(c, a, b0, b1) \
    asm volatile("mma.sync.aligned.m16n8k16.row.col.f32.bf16.bf16.f32 " \
        "{%0,%1,%2,%3}, {%4,%5,%6,%7}, {%8,%9}, {%0,%1,%2,%3};" \
        : "+f"((c)[0]), "+f"((c)[1]), "+f"((c)[2]), "+f"((c)[3]) \
        : "r"((a)[0]), "r"((a)[1]), "r"((a)[2]), "r"((a)[3]), "r"(b0), "r"(b1))

// ---------------- scratch -------------------------------------------------------
static __device__ __align__(16) float          g_h[(size_t)BATCH_N * 768];
static __device__ __align__(16) __nv_bfloat16  g_wbf[(size_t)BATCH_N * 1536];
static __device__ __align__(16) float          g_f[3][(size_t)BATCH_N * QD];
static __device__ __align__(16) __nv_bfloat16  g_b[3][(size_t)BATCH_N * 2 * QD];
static __device__ __align__(16) __nv_bfloat16  g_xbf[(size_t)BATCH_N * 2 * QD];
static __device__ __align__(16) __nv_bfloat16  g_wt[6553600];
static __device__ __align__(16) float          g_gate[4][8 * QD];

struct Epi {
    const float* bias;
    const float* cmat;
    const float* resmat;
    const float* lin; const float* p3; const float* p4; const float* p5;
    __nv_bfloat16* obf;
    int   kout;
    float alpha;
    int   blend;
};

enum { E_BIAS = 0, E_SILU = 1, E_TANH = 2, E_GATE = 3, E_NL = 4 };

// ---------------- tensor-core GEMM (mma.sync bf16, hi/lo 3-pass) ----------------
// C[M,N] = A[M,K] @ W[N,K]^T.  A: bf16 [M, 2K] (hi|lo), lda=2K.  W: bf16 [N, 2K].
#define BK 32
#define ROWB 80                     // smem row stride bytes (64B data + 16B skew)
#define STAGE_BYTES (128 * ROWB)    // per operand
#define NSTG 3
#define SMEM_DYN (NSTG * 2 * STAGE_BYTES)

template <int EPI>
__device__ __forceinline__ void epi_apply(float& x, int n, size_t co, const Epi& ep) {
    if (EPI == E_BIAS) {
        x += ep.bias[n];
    } else if (EPI == E_SILU) {
        x += ep.bias[n];
        x = x / (1.0f + __expf(-x));
    } else if (EPI == E_TANH) {
        x += ep.bias[n];
        x = tanhf(x);
    } else if (EPI == E_GATE) {
        const float c = ep.cmat[co];
        const float g = (ep.lin[n] * c
                         + 0.5f * __sinf(ep.p3[n] * c + ep.p4[n])
                         + 0.5f * __cosf(ep.p5[n] * c)) * 0.25f;
        x = (c + 0.3f * g + 0.2f * x) * (1.0f / 1.5f);
        if (ep.blend)
            x = ep.alpha * x + (1.0f - ep.alpha) * ep.resmat[co];
    } else if (EPI == E_NL) {
        x += ep.bias[n];
        const float c2 = ep.cmat[co];
        x = ep.alpha * (c2 + 0.1f * x) + (1.0f - ep.alpha) * ep.resmat[co];
    }
}

template <int EPI>
__global__ void __launch_bounds__(256, 2) gemm_mma(
    const __nv_bfloat16* __restrict__ A, int lda,
    const __nv_bfloat16* __restrict__ W, int ldb,
    float* __restrict__ C, int ldc, int K, Epi ep)
{
    extern __shared__ __align__(16) char dyns[];
    const uint32_t sbase = smem_u32(dyns);

    const int tid  = threadIdx.x;
    const int wid  = tid >> 5, lane = tid & 31;
    const int m0   = blockIdx.y * 128;
    const int n0   = blockIdx.x * 128;
    const int wm   = (wid >> 2) * 64;     // warp m offset within tile
    const int wn   = (wid & 3) * 32;      // warp n offset within tile

    const int kcn   = K / BK;
    const int iters = 3 * kcn;

    // per-thread cp.async mapping: 2 chunks for A, 2 for B
    const int c0 = tid, c1 = tid + 256;
    const int ar0 = c0 >> 2, ac0 = c0 & 3;
    const int ar1 = c1 >> 2, ac1 = c1 & 3;

    auto load_stage = [&](int s, int it) {
        const int p  = it / kcn;
        const int kc = it - p * kcn;
        const int ao = kc * BK + (p == 1 ? K : 0);   // pass1: A-lo
        const int bo = kc * BK + (p == 2 ? K : 0);   // pass2: B-lo
        const uint32_t smA = sbase + (uint32_t)s * 2 * STAGE_BYTES;
        const uint32_t smB = smA + STAGE_BYTES;
        CP_ASYNC16(smA + ar0 * ROWB + ac0 * 16, A + (size_t)(m0 + ar0) * lda + ao + ac0 * 8);
        CP_ASYNC16(smA + ar1 * ROWB + ac1 * 16, A + (size_t)(m0 + ar1) * lda + ao + ac1 * 8);
        CP_ASYNC16(smB + ar0 * ROWB + ac0 * 16, W + (size_t)(n0 + ar0) * ldb + bo + ac0 * 8);
        CP_ASYNC16(smB + ar1 * ROWB + ac1 * 16, W + (size_t)(n0 + ar1) * ldb + bo + ac1 * 8);
        CP_COMMIT();
    };

    float acc[4][4][4];
#pragma unroll
    for (int i = 0; i < 4; i++)
#pragma unroll
        for (int j = 0; j < 4; j++)
#pragma unroll
            for (int q = 0; q < 4; q++) acc[i][j][q] = 0.0f;

    load_stage(0, 0);
    if (iters > 1) load_stage(1, 1);

    const int lr = lane & 15, lc = lane >> 4;   // ldmatrix row / 16B-chunk select

    for (int it = 0; it < iters; ++it) {
        CP_WAIT1();
        __syncthreads();
        if (it + 2 < iters) load_stage((it + 2) % NSTG, it + 2);

        const uint32_t smA = sbase + (uint32_t)(it % NSTG) * 2 * STAGE_BYTES;
        const uint32_t smB = smA + STAGE_BYTES;

#pragma unroll
        for (int ks = 0; ks < 2; ks++) {
            uint32_t a[4][4], b[2][4];
#pragma unroll
            for (int mt = 0; mt < 4; mt++)
                LDSM_X4(a[mt], smA + (uint32_t)(wm + mt * 16 + lr) * ROWB + ks * 32 + lc * 16);
#pragma unroll
            for (int bt = 0; bt < 2; bt++)
                LDSM_X4(b[bt], smB + (uint32_t)(wn + bt * 16 + lr) * ROWB + ks * 32 + lc * 16);
#pragma unroll
            for (int mt = 0; mt < 4; mt++)
#pragma unroll
                for (int nt = 0; nt < 4; nt++)
                    MMA_BF16(acc[mt][nt], a[mt], b[nt >> 1][nt & 1], b[nt >> 1][(nt & 1) + 2]);
        }
        __syncthreads();
    }

    // ---------------- epilogue (fused) ----------------
    const int gid = lane >> 2, t4 = lane & 3;
#pragma unroll
    for (int mt = 0; mt < 4; mt++) {
#pragma unroll
        for (int half = 0; half < 2; half++) {
            const int m = m0 + wm + mt * 16 + gid + half * 8;
#pragma unroll
            for (int nt = 0; nt < 4; nt++) {
                const int n = n0 + wn + nt * 8 + t4 * 2;
                const size_t co = (size_t)m * ldc + n;
                float x0 = acc[mt][nt][half * 2];
                float x1 = acc[mt][nt][half * 2 + 1];
                epi_apply<EPI>(x0, n, co, ep);
                epi_apply<EPI>(x1, n + 1, co + 1, ep);
                if (C) *(float2*)&C[co] = make_float2(x0, x1);
                if (ep.obf) {
                    __nv_bfloat16* oh = ep.obf + (size_t)m * (2 * ep.kout) + n;
                    const __nv_bfloat16 h0 = __float2bfloat16(x0);
                    const __nv_bfloat16 h1 = __float2bfloat16(x1);
                    *(__nv_bfloat162*)oh = __nv_bfloat162(h0, h1);
                    *(__nv_bfloat162*)(oh + ep.kout) = __nv_bfloat162(
                        __float2bfloat16(x0 - __bfloat162float(h0)),
                        __float2bfloat16(x1 - __bfloat162float(h1)));
                }
            }
        }
    }
}

// ---------------- LayerNorm(768) + exact gelu -> bf16 hi/lo ---------------------
__global__ void ln_gelu_k(const float* __restrict__ h,
                          const float* __restrict__ w,
                          const float* __restrict__ b,
                          __nv_bfloat16* __restrict__ obf)
{
    const int row = blockIdx.x;
    const float* hr = h + (size_t)row * 768;
    const int t = threadIdx.x;

    const float v0 = hr[t], v1 = hr[t + 256], v2 = hr[t + 512];
    float s  = v0 + v1 + v2;
    float ss = v0 * v0 + v1 * v1 + v2 * v2;
#pragma unroll
    for (int o = 16; o > 0; o >>= 1) {
        s  += __shfl_down_sync(0xffffffffu, s, o);
        ss += __shfl_down_sync(0xffffffffu, ss, o);
    }
    __shared__ float rs[8], rss[8], mu_s, rstd_s;
    const int lane = t & 31, wp = t >> 5;
    if (lane == 0) { rs[wp] = s; rss[wp] = ss; }
    __syncthreads();
    if (t == 0) {
        float S = 0.0f, SS = 0.0f;
#pragma unroll
        for (int k = 0; k < 8; k++) { S += rs[k]; SS += rss[k]; }
        const float mu = S * (1.0f / 768.0f);
        mu_s = mu;
        rstd_s = rsqrtf(SS * (1.0f / 768.0f) - mu * mu + 1e-5f);
    }
    __syncthreads();
    const float mu = mu_s, rstd = rstd_s;

    __nv_bfloat16* orow = obf + (size_t)row * 1536;
#pragma unroll
    for (int k = 0; k < 3; k++) {
        const int c = t + k * 256;
        float x = (((k == 0) ? v0 : (k == 1) ? v1 : v2) - mu) * rstd * w[c] + b[c];
        x = 0.5f * x * (1.0f + erff(x * 0.70710678118654752f));
        const __nv_bfloat16 hi = __float2bfloat16(x);
        orow[c]       = hi;
        orow[768 + c] = __float2bfloat16(x - __bfloat162float(hi));
    }
}

// ---------------- row L2-normalize(256) + tanh (+ bf16 hi/lo) -------------------
__global__ void norm_tanh_k(const float* __restrict__ in, float* __restrict__ out,
                            __nv_bfloat16* __restrict__ obf)
{
    const int wp = threadIdx.x >> 5, lane = threadIdx.x & 31;
    const size_t row = (size_t)blockIdx.x * 8 + wp;
    const float* r = in + row * QD;
    const float4 a = *(const float4*)(r + lane * 4);
    const float4 c = *(const float4*)(r + 128 + lane * 4);
    float s = a.x * a.x + a.y * a.y + a.z * a.z + a.w * a.w
            + c.x * c.x + c.y * c.y + c.z * c.z + c.w * c.w;
#pragma unroll
    for (int o = 16; o > 0; o >>= 1) s += __shfl_xor_sync(0xffffffffu, s, o);
    const float inv = 1.0f / (sqrtf(s) + 1e-8f);

    float t[8];
    t[0] = tanhf(a.x * inv); t[1] = tanhf(a.y * inv);
    t[2] = tanhf(a.z * inv); t[3] = tanhf(a.w * inv);
    t[4] = tanhf(c.x * inv); t[5] = tanhf(c.y * inv);
    t[6] = tanhf(c.z * inv); t[7] = tanhf(c.w * inv);

    float* o = out + row * QD;
    *(float4*)(o + lane * 4)       = make_float4(t[0], t[1], t[2], t[3]);
    *(float4*)(o + 128 + lane * 4) = make_float4(t[4], t[5], t[6], t[7]);

    if (obf) {
        __nv_bfloat16* ob = obf + row * 512;
#pragma unroll
        for (int k = 0; k < 8; k++) {
            const int cc = (k < 4) ? (lane * 4 + k) : (128 + lane * 4 + k - 4);
            const __nv_bfloat16 hi = __float2bfloat16(t[k]);
            ob[cc]       = hi;
            ob[256 + cc] = __float2bfloat16(t[k] - __bfloat162float(hi));
        }
    }
}

// ---------------- conversions ---------------------------------------------------
__global__ void conv_x_k(const float* __restrict__ x, __nv_bfloat16* __restrict__ o)
{
    const size_t i = (size_t)blockIdx.x * 256 + threadIdx.x;
    const size_t m = i >> 8;
    const int    c = (int)(i & 255);
    const float v = x[i];
    const __nv_bfloat16 hi = __float2bfloat16(v);
    o[m * 512 + c]       = hi;
    o[m * 512 + 256 + c] = __float2bfloat16(v - __bfloat162float(hi));
}

// W [K,N] fp32 (optional col offset, optional tanh) -> [N, 2K] bf16 hi|lo
__global__ void conv_w_k(const float* __restrict__ src, size_t zs, int ldsrc, int coloff,
                         __nv_bfloat16* __restrict__ dst, size_t dzs,
                         int K, int N, int dotanh)
{
    const int n = blockIdx.x * 32 + threadIdx.x;
    const int k = blockIdx.y * 8 + threadIdx.y;
    if (n >= N || k >= K) return;
    const float* s = src + (size_t)blockIdx.z * zs;
    __nv_bfloat16* d = dst + (size_t)blockIdx.z * dzs;
    float v = s[(size_t)k * ldsrc + coloff + n];
    if (dotanh) v = tanhf(v);
    const __nv_bfloat16 hi = __float2bfloat16(v);
    d[(size_t)n * 2 * K + k]     = hi;
    d[(size_t)n * 2 * K + K + k] = __float2bfloat16(v - __bfloat162float(hi));
}

__global__ void prep_k(const float* __restrict__ gp, float* __restrict__ lin,
                       float* __restrict__ p3, float* __restrict__ p4,
                       float* __restrict__ p5)
{
    const int i = blockIdx.x * 256 + threadIdx.x;
    if (i < 8 * QD) {
        const float* p = gp + (size_t)i * 6;
        lin[i] = sinf(p[0]) + cosf(p[1]) + tanhf(p[2]);
        p3[i] = p[3]; p4[i] = p[4]; p5[i] = p[5];
    }
}

// ---------------- host ----------------------------------------------------------
static void launch_gemm(int epi, const __nv_bfloat16* A, int lda,
                        const __nv_bfloat16* W, int K, int N,
                        float* C, int ldc, const Epi& ep)
{
    dim3 grid(N / 128, BATCH_N / 128);
    dim3 blk(256);
    const int ldb = 2 * K;
    switch (epi) {
        case E_BIAS: gemm_mma<E_BIAS><<<grid, blk, SMEM_DYN>>>(A, lda, W, ldb, C, ldc, K, ep); break;
        case E_SILU: gemm_mma<E_SILU><<<grid, blk, SMEM_DYN>>>(A, lda, W, ldb, C, ldc, K, ep); break;
        case E_TANH: gemm_mma<E_TANH><<<grid, blk, SMEM_DYN>>>(A, lda, W, ldb, C, ldc, K, ep); break;
        case E_GATE: gemm_mma<E_GATE><<<grid, blk, SMEM_DYN>>>(A, lda, W, ldb, C, ldc, K, ep); break;
        case E_NL:   gemm_mma<E_NL>  <<<grid, blk, SMEM_DYN>>>(A, lda, W, ldb, C, ldc, K, ep); break;
    }
}

// bf16 weight-buffer element offsets
#define W01T 0u
#define W02T 1179648u
#define W11T 2359296u
#define W12T 3145728u
#define WVT  3932160u
#define WOT  4194304u
#define TENT 4456448u
#define NW1T 5505024u
#define NW2T 6029312u

extern "C" void kernel_launch(void* const* d_in, const int* in_sizes, int n_in,
                              void* d_out, int out_size)
{
    (void)in_sizes; (void)n_in; (void)out_size;
    const float* x    = (const float*)d_in[0];
    const float* w01  = (const float*)d_in[1];
    const float* b01  = (const float*)d_in[2];
    const float* lnw  = (const float*)d_in[3];
    const float* lnb  = (const float*)d_in[4];
    const float* w02  = (const float*)d_in[5];
    const float* b02  = (const float*)d_in[6];
    const float* w11  = (const float*)d_in[7];
    const float* b11  = (const float*)d_in[8];
    const float* w12  = (const float*)d_in[9];
    const float* b12  = (const float*)d_in[10];
    const float* wqkv = (const float*)d_in[11];
    const float* bqkv = (const float*)d_in[12];
    const float* wo   = (const float*)d_in[13];
    const float* bo   = (const float*)d_in[14];
    const float* gp   = (const float*)d_in[15];
    const float* ent  = (const float*)d_in[16];
    const float* nw1  = (const float*)d_in[17];
    const float* nb1  = (const float*)d_in[18];
    const float* nw2  = (const float*)d_in[19];
    const float* nb2  = (const float*)d_in[20];

    cudaFuncSetAttribute(gemm_mma<E_BIAS>, cudaFuncAttributeMaxDynamicSharedMemorySize, SMEM_DYN);
    cudaFuncSetAttribute(gemm_mma<E_SILU>, cudaFuncAttributeMaxDynamicSharedMemorySize, SMEM_DYN);
    cudaFuncSetAttribute(gemm_mma<E_TANH>, cudaFuncAttributeMaxDynamicSharedMemorySize, SMEM_DYN);
    cudaFuncSetAttribute(gemm_mma<E_GATE>, cudaFuncAttributeMaxDynamicSharedMemorySize, SMEM_DYN);
    cudaFuncSetAttribute(gemm_mma<E_NL>,   cudaFuncAttributeMaxDynamicSharedMemorySize, SMEM_DYN);

    float *H, *FB, *GATEB;
    __nv_bfloat16 *WBF, *BB, *XBF, *WT;
    cudaGetSymbolAddress((void**)&H,     g_h);
    cudaGetSymbolAddress((void**)&WBF,   g_wbf);
    cudaGetSymbolAddress((void**)&FB,    g_f);
    cudaGetSymbolAddress((void**)&BB,    g_b);
    cudaGetSymbolAddress((void**)&XBF,   g_xbf);
    cudaGetSymbolAddress((void**)&WT,    g_wt);
    cudaGetSymbolAddress((void**)&GATEB, g_gate);

    float* F[3]; __nv_bfloat16* Bf[3];
    for (int k = 0; k < 3; k++) {
        F[k]  = FB + (size_t)k * BATCH_N * QD;
        Bf[k] = BB + (size_t)k * BATCH_N * 2 * QD;
    }
    float* LIN = GATEB + 0 * 8 * QD;
    float* P3  = GATEB + 1 * 8 * QD;
    float* P4  = GATEB + 2 * 8 * QD;
    float* P5  = GATEB + 3 * 8 * QD;

    // ---- one-time conversions ----
    conv_x_k<<<BATCH_N, 256>>>(x, XBF);
    {
        dim3 b(32, 8);
        conv_w_k<<<dim3(24, 32, 3), b>>>(w01, (size_t)QD * 768, 768, 0, WT + W01T, 393216, QD, 768, 0);
        conv_w_k<<<dim3(8, 96, 3), b>>>(w02, (size_t)768 * QD, QD, 0, WT + W02T, 393216, 768, QD, 0);
        conv_w_k<<<dim3(16, 32, 3), b>>>(w11, (size_t)QD * 512, 512, 0, WT + W11T, 262144, QD, 512, 0);
        conv_w_k<<<dim3(8, 64, 3), b>>>(w12, (size_t)512 * QD, QD, 0, WT + W12T, 262144, 512, QD, 0);
        conv_w_k<<<dim3(8, 32, 2), b>>>(wqkv, (size_t)QD * 768, 768, 512, WT + WVT, 131072, QD, QD, 0);
        conv_w_k<<<dim3(8, 32, 2), b>>>(wo, (size_t)QD * QD, QD, 0, WT + WOT, 131072, QD, QD, 0);
        conv_w_k<<<dim3(8, 32, 8), b>>>(ent, (size_t)QD * QD, QD, 0, WT + TENT, 131072, QD, QD, 1);
        conv_w_k<<<dim3(8, 32, 4), b>>>(nw1, (size_t)QD * QD, QD, 0, WT + NW1T, 131072, QD, QD, 0);
        conv_w_k<<<dim3(8, 32, 4), b>>>(nw2, (size_t)QD * QD, QD, 0, WT + NW2T, 131072, QD, QD, 0);
    }
    prep_k<<<8, 256>>>(gp, LIN, P3, P4, P5);

    float* cur = (float*)x;
    const __nv_bfloat16* curbf = XBF;
    int scur = -1;

    for (int li = 0; li < 8; li++) {
        int s0 = -1, s1 = -1;
        for (int k = 0; k < 3; k++)
            if (k != scur) { if (s0 < 0) s0 = k; else if (s1 < 0) s1 = k; }
        float* F0 = F[s0]; float* F1 = F[s1];
        __nv_bfloat16* B0 = Bf[s0]; __nv_bfloat16* B1 = Bf[s1];

        const int t = li % 3;
        const int odd = li & 1;
        const float alpha = (li < 4) ? 0.8f : 0.6f;

        if (t == 0) {
            const int i = li / 3;
            Epi e = {}; e.bias = b01 + i * 768;
            launch_gemm(E_BIAS, curbf, 512, WT + W01T + (size_t)i * 393216, QD, 768, H, 768, e);
            ln_gelu_k<<<BATCH_N, 256>>>(H, lnw + i * 768, lnb + i * 768, WBF);
            Epi e2 = {}; e2.bias = b02 + i * QD; e2.obf = B0; e2.kout = QD;
            launch_gemm(E_BIAS, WBF, 1536, WT + W02T + (size_t)i * 393216, 768, QD, F0, QD, e2);
        } else if (t == 1) {
            const int i = (li - 1) / 3;
            Epi e = {}; e.bias = b11 + i * 512; e.obf = WBF; e.kout = 512;
            launch_gemm(E_SILU, curbf, 512, WT + W11T + (size_t)i * 262144, QD, 512, nullptr, 512, e);
            Epi e2 = {}; e2.bias = b12 + i * QD; e2.obf = B0; e2.kout = QD;
            launch_gemm(E_BIAS, WBF, 1024, WT + W12T + (size_t)i * 262144, 512, QD, F0, QD, e2);
        } else {
            const int i = (li - 2) / 3;
            Epi e = {}; e.bias = bqkv + i * 768 + 512; e.obf = B1; e.kout = QD;
            launch_gemm(E_BIAS, curbf, 512, WT + WVT + (size_t)i * 131072, QD, QD, nullptr, QD, e);
            Epi e2 = {}; e2.bias = bo + i * QD; e2.obf = B0; e2.kout = QD;
            launch_gemm(E_BIAS, B1, 512, WT + WOT + (size_t)i * 131072, QD, QD, F0, QD, e2);
        }

        // entangle + gate (+ blend on even layers)
        Epi eg = {};
        eg.cmat = F0; eg.resmat = cur;
        eg.lin = LIN + li * QD; eg.p3 = P3 + li * QD;
        eg.p4 = P4 + li * QD;   eg.p5 = P5 + li * QD;
        eg.alpha = alpha; eg.blend = !odd;
        if (odd) { eg.obf = B1; eg.kout = QD; }
        launch_gemm(E_GATE, B0, 512, WT + TENT + (size_t)li * 131072, QD, QD, F1, QD, eg);

        if (odd) {
            const int j = li / 2;
            Epi et = {}; et.bias = nb1 + j * QD; et.obf = WBF; et.kout = QD;
            launch_gemm(E_TANH, B1, 512, WT + NW1T + (size_t)j * 131072, QD, QD, nullptr, QD, et);
            Epi en = {}; en.bias = nb2 + j * QD;
            en.cmat = F1; en.resmat = cur; en.alpha = alpha;
            launch_gemm(E_NL, WBF, 512, WT + NW2T + (size_t)j * 131072, QD, QD, F1, QD, en);
        }

        if (li == 7) {
            norm_tanh_k<<<BATCH_N / 8, 256>>>(F1, (float*)d_out, nullptr);
            cur = (float*)d_out;
        } else {
            norm_tanh_k<<<BATCH_N / 8, 256>>>(F1, F1, B1);
            cur = F1; curbf = B1; scur = s1;
        }
    }
}

// round 5
// speedup vs baseline: 2.8764x; 1.6852x over previous
#include <cuda_runtime.h>
#include <cuda_bf16.h>
#include <math.h>
#include <stdint.h>
#include <stddef.h>

#define BATCH_N 65536
#define QD      256

// ---------------- ptx helpers ---------------------------------------------------
__device__ __forceinline__ uint32_t smem_u32(const void* p) {
    uint32_t a;
    asm("{ .reg .u64 t; cvta.to.shared.u64 t, %1; cvt.u32.u64 %0, t; }" : "=r"(a) : "l"(p));
    return a;
}

#define CP_ASYNC16(dst, src) \
    asm volatile("cp.async.cg.shared.global [%0], [%1], 16;" :: "r"(dst), "l"(src) : "memory")
#define CP_COMMIT() asm volatile("cp.async.commit_group;" ::: "memory")
#define CP_WAIT1()  asm volatile("cp.async.wait_group 1;" ::: "memory")

#define LDSM_X4(r, addr) \
    asm volatile("ldmatrix.sync.aligned.m8n8.x4.shared.b16 {%0,%1,%2,%3}, [%4];" \
        : "=r"((r)[0]), "=r"((r)[1]), "=r"((r)[2]), "=r"((r)[3]) : "r"(addr))

#define MMA_BF16(c, a, b0, b1) \
    asm volatile("mma.sync.aligned.m16n8k16.row.col.f32.bf16.bf16.f32 " \
        "{%0,%1,%2,%3}, {%4,%5,%6,%7}, {%8,%9}, {%0,%1,%2,%3};" \
        : "+f"((c)[0]), "+f"((c)[1]), "+f"((c)[2]), "+f"((c)[3]) \
        : "r"((a)[0]), "r"((a)[1]), "r"((a)[2]), "r"((a)[3]), "r"(b0), "r"(b1))

// ---------------- scratch -------------------------------------------------------
static __device__ __align__(16) float          g_h[(size_t)BATCH_N * 768];
static __device__ __align__(16) __nv_bfloat16  g_wbf[(size_t)BATCH_N * 1536];
static __device__ __align__(16) float          g_f[3][(size_t)BATCH_N * QD];
static __device__ __align__(16) __nv_bfloat16  g_b[3][(size_t)BATCH_N * 2 * QD];
static __device__ __align__(16) __nv_bfloat16  g_xbf[(size_t)BATCH_N * 2 * QD];
static __device__ __align__(16) __nv_bfloat16  g_wt[6553600];
static __device__ __align__(16) float          g_gate[4][8 * QD];

struct Epi {
    const float* bias;
    const float* cmat;
    const float* resmat;
    const float* lin; const float* p3; const float* p4; const float* p5;
    __nv_bfloat16* obf;
    int   kout;
    float alpha;
    int   blend;
};

enum { E_BIAS = 0, E_SILU = 1, E_TANH = 2, E_GATE = 3, E_NL = 4 };

// ---------------- tensor-core GEMM (mma.sync bf16, hi/lo 3-pass) ----------------
// C[M,N] = A[M,K] @ W[N,K]^T.  A: bf16 [M, 2K] (hi|lo), lda=2K.  W: bf16 [N, 2K].
#define BK 64
#define ROWB 144                     // 128B data + 16B skew (slot pattern 9r+c mod 8)
#define OP_BYTES (128 * ROWB)        // one operand tile (128 rows x 144B)
#define STAGE_BYTES (2 * OP_BYTES)   // A + B
#define NSTG 3
#define SMEM_DYN (NSTG * STAGE_BYTES)

template <int EPI>
__device__ __forceinline__ void epi_apply(float& x, int n, size_t co, const Epi& ep) {
    if (EPI == E_BIAS) {
        x += ep.bias[n];
    } else if (EPI == E_SILU) {
        x += ep.bias[n];
        x = x / (1.0f + __expf(-x));
    } else if (EPI == E_TANH) {
        x += ep.bias[n];
        x = tanhf(x);
    } else if (EPI == E_GATE) {
        const float c = ep.cmat[co];
        const float g = (ep.lin[n] * c
                         + 0.5f * __sinf(ep.p3[n] * c + ep.p4[n])
                         + 0.5f * __cosf(ep.p5[n] * c)) * 0.25f;
        x = (c + 0.3f * g + 0.2f * x) * (1.0f / 1.5f);
        if (ep.blend)
            x = ep.alpha * x + (1.0f - ep.alpha) * ep.resmat[co];
    } else if (EPI == E_NL) {
        x += ep.bias[n];
        const float c2 = ep.cmat[co];
        x = ep.alpha * (c2 + 0.1f * x) + (1.0f - ep.alpha) * ep.resmat[co];
    }
}

template <int EPI>
__global__ void __launch_bounds__(256, 2) gemm_mma(
    const __nv_bfloat16* __restrict__ A, int lda,
    const __nv_bfloat16* __restrict__ W, int ldb,
    float* __restrict__ C, int ldc, int K, Epi ep)
{
    extern __shared__ __align__(16) char dyns[];
    const uint32_t sbase = smem_u32(dyns);

    const int tid  = threadIdx.x;
    const int wid  = tid >> 5, lane = tid & 31;
    const int m0   = blockIdx.y * 128;
    const int n0   = blockIdx.x * 128;
    const int wm   = (wid >> 2) * 64;     // warp m offset
    const int wn   = (wid & 3) * 32;      // warp n offset

    const int kcn   = K / BK;
    const int iters = 3 * kcn;

    // cp.async mapping: 128 rows x 8 x 16B chunks per operand; 4 chunks/thread each
    const int crow = tid >> 3;            // over i: row = crow + i*32
    const int ccol = (tid & 7) * 16;      // byte col within 128B
    const int gcol = (tid & 7) * 8;       // element col (bf16)

    auto load_stage = [&](int s, int it) {
        const int p  = it / kcn;
        const int kc = it - p * kcn;
        const int ao = kc * BK + (p == 1 ? K : 0);   // pass1: A-lo
        const int bo = kc * BK + (p == 2 ? K : 0);   // pass2: B-lo
        const uint32_t smA = sbase + (uint32_t)s * STAGE_BYTES;
        const uint32_t smB = smA + OP_BYTES;
        const __nv_bfloat16* ga = A + (size_t)(m0 + crow) * lda + ao + gcol;
        const __nv_bfloat16* gb = W + (size_t)(n0 + crow) * ldb + bo + gcol;
#pragma unroll
        for (int i = 0; i < 4; i++)
            CP_ASYNC16(smA + (uint32_t)(crow + i * 32) * ROWB + ccol, ga + (size_t)(i * 32) * lda);
#pragma unroll
        for (int i = 0; i < 4; i++)
            CP_ASYNC16(smB + (uint32_t)(crow + i * 32) * ROWB + ccol, gb + (size_t)(i * 32) * ldb);
        CP_COMMIT();
    };

    float acc[4][4][4];
#pragma unroll
    for (int i = 0; i < 4; i++)
#pragma unroll
        for (int j = 0; j < 4; j++)
#pragma unroll
            for (int q = 0; q < 4; q++) acc[i][j][q] = 0.0f;

    load_stage(0, 0);
    if (iters > 1) load_stage(1, 1);

    const int lr = lane & 15, lc = lane >> 4;   // ldmatrix row / 16B-chunk select

    for (int it = 0; it < iters; ++it) {
        CP_WAIT1();
        __syncthreads();
        if (it + 2 < iters) load_stage((it + 2) % NSTG, it + 2);

        const uint32_t smA = sbase + (uint32_t)(it % NSTG) * STAGE_BYTES;
        const uint32_t smB = smA + OP_BYTES;

#pragma unroll
        for (int ks = 0; ks < 4; ks++) {
            uint32_t a[4][4], b[2][4];
#pragma unroll
            for (int mt = 0; mt < 4; mt++)
                LDSM_X4(a[mt], smA + (uint32_t)(wm + mt * 16 + lr) * ROWB + ks * 32 + lc * 16);
#pragma unroll
            for (int bt = 0; bt < 2; bt++)
                LDSM_X4(b[bt], smB + (uint32_t)(wn + bt * 16 + lr) * ROWB + ks * 32 + lc * 16);
#pragma unroll
            for (int mt = 0; mt < 4; mt++)
#pragma unroll
                for (int nt = 0; nt < 4; nt++)
                    MMA_BF16(acc[mt][nt], a[mt], b[nt >> 1][nt & 1], b[nt >> 1][(nt & 1) + 2]);
        }
    }

    // ---------------- epilogue (fused) ----------------
    const int gid = lane >> 2, t4 = lane & 3;
#pragma unroll
    for (int mt = 0; mt < 4; mt++) {
#pragma unroll
        for (int half = 0; half < 2; half++) {
            const int m = m0 + wm + mt * 16 + gid + half * 8;
#pragma unroll
            for (int nt = 0; nt < 4; nt++) {
                const int n = n0 + wn + nt * 8 + t4 * 2;
                const size_t co = (size_t)m * ldc + n;
                float x0 = acc[mt][nt][half * 2];
                float x1 = acc[mt][nt][half * 2 + 1];
                epi_apply<EPI>(x0, n, co, ep);
                epi_apply<EPI>(x1, n + 1, co + 1, ep);
                if (C) *(float2*)&C[co] = make_float2(x0, x1);
                if (ep.obf) {
                    __nv_bfloat16* oh = ep.obf + (size_t)m * (2 * ep.kout) + n;
                    const __nv_bfloat16 h0 = __float2bfloat16(x0);
                    const __nv_bfloat16 h1 = __float2bfloat16(x1);
                    *(__nv_bfloat162*)oh = __nv_bfloat162(h0, h1);
                    *(__nv_bfloat162*)(oh + ep.kout) = __nv_bfloat162(
                        __float2bfloat16(x0 - __bfloat162float(h0)),
                        __float2bfloat16(x1 - __bfloat162float(h1)));
                }
            }
        }
    }
}

// ---------------- LayerNorm(768) + exact gelu -> bf16 hi/lo ---------------------
__global__ void ln_gelu_k(const float* __restrict__ h,
                          const float* __restrict__ w,
                          const float* __restrict__ b,
                          __nv_bfloat16* __restrict__ obf)
{
    const int row = blockIdx.x;
    const float* hr = h + (size_t)row * 768;
    const int t = threadIdx.x;

    const float v0 = hr[t], v1 = hr[t + 256], v2 = hr[t + 512];
    float s  = v0 + v1 + v2;
    float ss = v0 * v0 + v1 * v1 + v2 * v2;
#pragma unroll
    for (int o = 16; o > 0; o >>= 1) {
        s  += __shfl_down_sync(0xffffffffu, s, o);
        ss += __shfl_down_sync(0xffffffffu, ss, o);
    }
    __shared__ float rs[8], rss[8], mu_s, rstd_s;
    const int lane = t & 31, wp = t >> 5;
    if (lane == 0) { rs[wp] = s; rss[wp] = ss; }
    __syncthreads();
    if (t == 0) {
        float S = 0.0f, SS = 0.0f;
#pragma unroll
        for (int k = 0; k < 8; k++) { S += rs[k]; SS += rss[k]; }
        const float mu = S * (1.0f / 768.0f);
        mu_s = mu;
        rstd_s = rsqrtf(SS * (1.0f / 768.0f) - mu * mu + 1e-5f);
    }
    __syncthreads();
    const float mu = mu_s, rstd = rstd_s;

    __nv_bfloat16* orow = obf + (size_t)row * 1536;
#pragma unroll
    for (int k = 0; k < 3; k++) {
        const int c = t + k * 256;
        float x = (((k == 0) ? v0 : (k == 1) ? v1 : v2) - mu) * rstd * w[c] + b[c];
        x = 0.5f * x * (1.0f + erff(x * 0.70710678118654752f));
        const __nv_bfloat16 hi = __float2bfloat16(x);
        orow[c]       = hi;
        orow[768 + c] = __float2bfloat16(x - __bfloat162float(hi));
    }
}

// ---------------- row L2-normalize(256) + tanh (+ bf16 hi/lo) -------------------
__global__ void norm_tanh_k(const float* __restrict__ in, float* __restrict__ out,
                            __nv_bfloat16* __restrict__ obf)
{
    const int wp = threadIdx.x >> 5, lane = threadIdx.x & 31;
    const size_t row = (size_t)blockIdx.x * 8 + wp;
    const float* r = in + row * QD;
    const float4 a = *(const float4*)(r + lane * 4);
    const float4 c = *(const float4*)(r + 128 + lane * 4);
    float s = a.x * a.x + a.y * a.y + a.z * a.z + a.w * a.w
            + c.x * c.x + c.y * c.y + c.z * c.z + c.w * c.w;
#pragma unroll
    for (int o = 16; o > 0; o >>= 1) s += __shfl_xor_sync(0xffffffffu, s, o);
    const float inv = 1.0f / (sqrtf(s) + 1e-8f);

    float t[8];
    t[0] = tanhf(a.x * inv); t[1] = tanhf(a.y * inv);
    t[2] = tanhf(a.z * inv); t[3] = tanhf(a.w * inv);
    t[4] = tanhf(c.x * inv); t[5] = tanhf(c.y * inv);
    t[6] = tanhf(c.z * inv); t[7] = tanhf(c.w * inv);

    float* o = out + row * QD;
    *(float4*)(o + lane * 4)       = make_float4(t[0], t[1], t[2], t[3]);
    *(float4*)(o + 128 + lane * 4) = make_float4(t[4], t[5], t[6], t[7]);

    if (obf) {
        __nv_bfloat16* ob = obf + row * 512;
#pragma unroll
        for (int k = 0; k < 8; k++) {
            const int cc = (k < 4) ? (lane * 4 + k) : (128 + lane * 4 + k - 4);
            const __nv_bfloat16 hi = __float2bfloat16(t[k]);
            ob[cc]       = hi;
            ob[256 + cc] = __float2bfloat16(t[k] - __bfloat162float(hi));
        }
    }
}

// ---------------- conversions ---------------------------------------------------
__global__ void conv_x_k(const float* __restrict__ x, __nv_bfloat16* __restrict__ o)
{
    const size_t i = (size_t)blockIdx.x * 256 + threadIdx.x;
    const size_t m = i >> 8;
    const int    c = (int)(i & 255);
    const float v = x[i];
    const __nv_bfloat16 hi = __float2bfloat16(v);
    o[m * 512 + c]       = hi;
    o[m * 512 + 256 + c] = __float2bfloat16(v - __bfloat162float(hi));
}

// W [K,N] fp32 (optional col offset, optional tanh) -> [N, 2K] bf16 hi|lo
__global__ void conv_w_k(const float* __restrict__ src, size_t zs, int ldsrc, int coloff,
                         __nv_bfloat16* __restrict__ dst, size_t dzs,
                         int K, int N, int dotanh)
{
    const int n = blockIdx.x * 32 + threadIdx.x;
    const int k = blockIdx.y * 8 + threadIdx.y;
    if (n >= N || k >= K) return;
    const float* s = src + (size_t)blockIdx.z * zs;
    __nv_bfloat16* d = dst + (size_t)blockIdx.z * dzs;
    float v = s[(size_t)k * ldsrc + coloff + n];
    if (dotanh) v = tanhf(v);
    const __nv_bfloat16 hi = __float2bfloat16(v);
    d[(size_t)n * 2 * K + k]     = hi;
    d[(size_t)n * 2 * K + K + k] = __float2bfloat16(v - __bfloat162float(hi));
}

__global__ void prep_k(const float* __restrict__ gp, float* __restrict__ lin,
                       float* __restrict__ p3, float* __restrict__ p4,
                       float* __restrict__ p5)
{
    const int i = blockIdx.x * 256 + threadIdx.x;
    if (i < 8 * QD) {
        const float* p = gp + (size_t)i * 6;
        lin[i] = sinf(p[0]) + cosf(p[1]) + tanhf(p[2]);
        p3[i] = p[3]; p4[i] = p[4]; p5[i] = p[5];
    }
}

// ---------------- host ----------------------------------------------------------
static void launch_gemm(int epi, const __nv_bfloat16* A, int lda,
                        const __nv_bfloat16* W, int K, int N,
                        float* C, int ldc, const Epi& ep)
{
    dim3 grid(N / 128, BATCH_N / 128);
    dim3 blk(256);
    const int ldb = 2 * K;
    switch (epi) {
        case E_BIAS: gemm_mma<E_BIAS><<<grid, blk, SMEM_DYN>>>(A, lda, W, ldb, C, ldc, K, ep); break;
        case E_SILU: gemm_mma<E_SILU><<<grid, blk, SMEM_DYN>>>(A, lda, W, ldb, C, ldc, K, ep); break;
        case E_TANH: gemm_mma<E_TANH><<<grid, blk, SMEM_DYN>>>(A, lda, W, ldb, C, ldc, K, ep); break;
        case E_GATE: gemm_mma<E_GATE><<<grid, blk, SMEM_DYN>>>(A, lda, W, ldb, C, ldc, K, ep); break;
        case E_NL:   gemm_mma<E_NL>  <<<grid, blk, SMEM_DYN>>>(A, lda, W, ldb, C, ldc, K, ep); break;
    }
}

// bf16 weight-buffer element offsets
#define W01T 0u
#define W02T 1179648u
#define W11T 2359296u
#define W12T 3145728u
#define WVT  3932160u
#define WOT  4194304u
#define TENT 4456448u
#define NW1T 5505024u
#define NW2T 6029312u

extern "C" void kernel_launch(void* const* d_in, const int* in_sizes, int n_in,
                              void* d_out, int out_size)
{
    (void)in_sizes; (void)n_in; (void)out_size;
    const float* x    = (const float*)d_in[0];
    const float* w01  = (const float*)d_in[1];
    const float* b01  = (const float*)d_in[2];
    const float* lnw  = (const float*)d_in[3];
    const float* lnb  = (const float*)d_in[4];
    const float* w02  = (const float*)d_in[5];
    const float* b02  = (const float*)d_in[6];
    const float* w11  = (const float*)d_in[7];
    const float* b11  = (const float*)d_in[8];
    const float* w12  = (const float*)d_in[9];
    const float* b12  = (const float*)d_in[10];
    const float* wqkv = (const float*)d_in[11];
    const float* bqkv = (const float*)d_in[12];
    const float* wo   = (const float*)d_in[13];
    const float* bo   = (const float*)d_in[14];
    const float* gp   = (const float*)d_in[15];
    const float* ent  = (const float*)d_in[16];
    const float* nw1  = (const float*)d_in[17];
    const float* nb1  = (const float*)d_in[18];
    const float* nw2  = (const float*)d_in[19];
    const float* nb2  = (const float*)d_in[20];

    cudaFuncSetAttribute(gemm_mma<E_BIAS>, cudaFuncAttributeMaxDynamicSharedMemorySize, SMEM_DYN);
    cudaFuncSetAttribute(gemm_mma<E_SILU>, cudaFuncAttributeMaxDynamicSharedMemorySize, SMEM_DYN);
    cudaFuncSetAttribute(gemm_mma<E_TANH>, cudaFuncAttributeMaxDynamicSharedMemorySize, SMEM_DYN);
    cudaFuncSetAttribute(gemm_mma<E_GATE>, cudaFuncAttributeMaxDynamicSharedMemorySize, SMEM_DYN);
    cudaFuncSetAttribute(gemm_mma<E_NL>,   cudaFuncAttributeMaxDynamicSharedMemorySize, SMEM_DYN);

    float *H, *FB, *GATEB;
    __nv_bfloat16 *WBF, *BB, *XBF, *WT;
    cudaGetSymbolAddress((void**)&H,     g_h);
    cudaGetSymbolAddress((void**)&WBF,   g_wbf);
    cudaGetSymbolAddress((void**)&FB,    g_f);
    cudaGetSymbolAddress((void**)&BB,    g_b);
    cudaGetSymbolAddress((void**)&XBF,   g_xbf);
    cudaGetSymbolAddress((void**)&WT,    g_wt);
    cudaGetSymbolAddress((void**)&GATEB, g_gate);

    float* F[3]; __nv_bfloat16* Bf[3];
    for (int k = 0; k < 3; k++) {
        F[k]  = FB + (size_t)k * BATCH_N * QD;
        Bf[k] = BB + (size_t)k * BATCH_N * 2 * QD;
    }
    float* LIN = GATEB + 0 * 8 * QD;
    float* P3  = GATEB + 1 * 8 * QD;
    float* P4  = GATEB + 2 * 8 * QD;
    float* P5  = GATEB + 3 * 8 * QD;

    // ---- one-time conversions ----
    conv_x_k<<<BATCH_N, 256>>>(x, XBF);
    {
        dim3 b(32, 8);
        conv_w_k<<<dim3(24, 32, 3), b>>>(w01, (size_t)QD * 768, 768, 0, WT + W01T, 393216, QD, 768, 0);
        conv_w_k<<<dim3(8, 96, 3), b>>>(w02, (size_t)768 * QD, QD, 0, WT + W02T, 393216, 768, QD, 0);
        conv_w_k<<<dim3(16, 32, 3), b>>>(w11, (size_t)QD * 512, 512, 0, WT + W11T, 262144, QD, 512, 0);
        conv_w_k<<<dim3(8, 64, 3), b>>>(w12, (size_t)512 * QD, QD, 0, WT + W12T, 262144, 512, QD, 0);
        conv_w_k<<<dim3(8, 32, 2), b>>>(wqkv, (size_t)QD * 768, 768, 512, WT + WVT, 131072, QD, QD, 0);
        conv_w_k<<<dim3(8, 32, 2), b>>>(wo, (size_t)QD * QD, QD, 0, WT + WOT, 131072, QD, QD, 0);
        conv_w_k<<<dim3(8, 32, 8), b>>>(ent, (size_t)QD * QD, QD, 0, WT + TENT, 131072, QD, QD, 1);
        conv_w_k<<<dim3(8, 32, 4), b>>>(nw1, (size_t)QD * QD, QD, 0, WT + NW1T, 131072, QD, QD, 0);
        conv_w_k<<<dim3(8, 32, 4), b>>>(nw2, (size_t)QD * QD, QD, 0, WT + NW2T, 131072, QD, QD, 0);
    }
    prep_k<<<8, 256>>>(gp, LIN, P3, P4, P5);

    float* cur = (float*)x;
    const __nv_bfloat16* curbf = XBF;
    int scur = -1;

    for (int li = 0; li < 8; li++) {
        int s0 = -1, s1 = -1;
        for (int k = 0; k < 3; k++)
            if (k != scur) { if (s0 < 0) s0 = k; else if (s1 < 0) s1 = k; }
        float* F0 = F[s0]; float* F1 = F[s1];
        __nv_bfloat16* B0 = Bf[s0]; __nv_bfloat16* B1 = Bf[s1];

        const int t = li % 3;
        const int odd = li & 1;
        const float alpha = (li < 4) ? 0.8f : 0.6f;

        if (t == 0) {
            const int i = li / 3;
            Epi e = {}; e.bias = b01 + i * 768;
            launch_gemm(E_BIAS, curbf, 512, WT + W01T + (size_t)i * 393216, QD, 768, H, 768, e);
            ln_gelu_k<<<BATCH_N, 256>>>(H, lnw + i * 768, lnb + i * 768, WBF);
            Epi e2 = {}; e2.bias = b02 + i * QD; e2.obf = B0; e2.kout = QD;
            launch_gemm(E_BIAS, WBF, 1536, WT + W02T + (size_t)i * 393216, 768, QD, F0, QD, e2);
        } else if (t == 1) {
            const int i = (li - 1) / 3;
            Epi e = {}; e.bias = b11 + i * 512; e.obf = WBF; e.kout = 512;
            launch_gemm(E_SILU, curbf, 512, WT + W11T + (size_t)i * 262144, QD, 512, nullptr, 512, e);
            Epi e2 = {}; e2.bias = b12 + i * QD; e2.obf = B0; e2.kout = QD;
            launch_gemm(E_BIAS, WBF, 1024, WT + W12T + (size_t)i * 262144, 512, QD, F0, QD, e2);
        } else {
            const int i = (li - 2) / 3;
            Epi e = {}; e.bias = bqkv + i * 768 + 512; e.obf = B1; e.kout = QD;
            launch_gemm(E_BIAS, curbf, 512, WT + WVT + (size_t)i * 131072, QD, QD, nullptr, QD, e);
            Epi e2 = {}; e2.bias = bo + i * QD; e2.obf = B0; e2.kout = QD;
            launch_gemm(E_BIAS, B1, 512, WT + WOT + (size_t)i * 131072, QD, QD, F0, QD, e2);
        }

        // entangle + gate (+ blend on even layers)
        Epi eg = {};
        eg.cmat = F0; eg.resmat = cur;
        eg.lin = LIN + li * QD; eg.p3 = P3 + li * QD;
        eg.p4 = P4 + li * QD;   eg.p5 = P5 + li * QD;
        eg.alpha = alpha; eg.blend = !odd;
        if (odd) { eg.obf = B1; eg.kout = QD; }
        launch_gemm(E_GATE, B0, 512, WT + TENT + (size_t)li * 131072, QD, QD, F1, QD, eg);

        if (odd) {
            const int j = li / 2;
            Epi et = {}; et.bias = nb1 + j * QD; et.obf = WBF; et.kout = QD;
            launch_gemm(E_TANH, B1, 512, WT + NW1T + (size_t)j * 131072, QD, QD, nullptr, QD, et);
            Epi en = {}; en.bias = nb2 + j * QD;
            en.cmat = F1; en.resmat = cur; en.alpha = alpha;
            launch_gemm(E_NL, WBF, 512, WT + NW2T + (size_t)j * 131072, QD, QD, F1, QD, en);
        }

        if (li == 7) {
            norm_tanh_k<<<BATCH_N / 8, 256>>>(F1, (float*)d_out, nullptr);
            cur = (float*)d_out;
        } else {
            norm_tanh_k<<<BATCH_N / 8, 256>>>(F1, F1, B1);
            cur = F1; curbf = B1; scur = s1;
        }
    }
}

// round 6
// speedup vs baseline: 3.5600x; 1.2377x over previous
#include <cuda_runtime.h>
#include <cuda_bf16.h>
#include <math.h>
#include <stdint.h>
#include <stddef.h>

#define BATCH_N 65536
#define QD      256

// ---------------- ptx helpers ---------------------------------------------------
__device__ __forceinline__ uint32_t smem_u32(const void* p) {
    uint32_t a;
    asm("{ .reg .u64 t; cvta.to.shared.u64 t, %1; cvt.u32.u64 %0, t; }" : "=r"(a) : "l"(p));
    return a;
}

#define CP_ASYNC16(dst, src) \
    asm volatile("cp.async.cg.shared.global [%0], [%1], 16;" :: "r"(dst), "l"(src) : "memory")
#define CP_COMMIT() asm volatile("cp.async.commit_group;" ::: "memory")
#define CP_WAIT1()  asm volatile("cp.async.wait_group 1;" ::: "memory")

#define LDSM_X4(r, addr) \
    asm volatile("ldmatrix.sync.aligned.m8n8.x4.shared.b16 {%0,%1,%2,%3}, [%4];" \
        : "=r"((r)[0]), "=r"((r)[1]), "=r"((r)[2]), "=r"((r)[3]) : "r"(addr))

#define MMA_TF32(c, a, b0, b1) \
    asm volatile("mma.sync.aligned.m16n8k8.row.col.f32.tf32.tf32.f32 " \
        "{%0,%1,%2,%3}, {%4,%5,%6,%7}, {%8,%9}, {%0,%1,%2,%3};" \
        : "+f"((c)[0]), "+f"((c)[1]), "+f"((c)[2]), "+f"((c)[3]) \
        : "r"((a)[0]), "r"((a)[1]), "r"((a)[2]), "r"((a)[3]), "r"(b0), "r"(b1))

#define CVT_TF32(r) asm volatile("cvt.rna.tf32.f32 %0, %0;" : "+r"(r))

__device__ __forceinline__ float tf32r(float v) {
    asm("cvt.rna.tf32.f32 %0, %0;" : "+f"(v));
    return v;
}

// ---------------- scratch -------------------------------------------------------
static __device__ __align__(16) float g_h[(size_t)BATCH_N * 768];
static __device__ __align__(16) float g_f[3][(size_t)BATCH_N * QD];
static __device__ __align__(16) float g_wtf[3276800];   // all transposed tf32 weights
static __device__ __align__(16) float g_gate[4][8 * QD];

struct Epi {
    const float* bias;
    const float* cmat;
    const float* resmat;
    const float* lin; const float* p3; const float* p4; const float* p5;
    float alpha;
    int   blend;
};

enum { E_BIAS = 0, E_SILU = 1, E_TANH = 2, E_GATE = 3, E_NL = 4 };

// ---------------- tensor-core GEMM (mma.sync tf32, single pass) -----------------
// C[M,N] = A[M,K] @ W[N,K]^T.  A: fp32 [M,K].  W: fp32 (tf32-rounded) [N,K].
// CTA tile 256x128, 512 threads, BK=32, 3-stage cp.async pipeline.
#define BK 32
#define ROWB 144                       // 128B data + 16B skew
#define OP_A (256 * ROWB)
#define OP_B (128 * ROWB)
#define STAGE_BYTES (OP_A + OP_B)
#define NSTG 3
#define SMEM_DYN (NSTG * STAGE_BYTES)  // 165888

template <int EPI>
__device__ __forceinline__ void epi_apply(float& x, int n, size_t co, const Epi& ep) {
    if (EPI == E_BIAS) {
        x += ep.bias[n];
    } else if (EPI == E_SILU) {
        x += ep.bias[n];
        x = x / (1.0f + __expf(-x));
    } else if (EPI == E_TANH) {
        x += ep.bias[n];
        x = tanhf(x);
    } else if (EPI == E_GATE) {
        const float c = ep.cmat[co];
        const float g = (ep.lin[n] * c
                         + 0.5f * __sinf(ep.p3[n] * c + ep.p4[n])
                         + 0.5f * __cosf(ep.p5[n] * c)) * 0.25f;
        x = (c + 0.3f * g + 0.2f * x) * (1.0f / 1.5f);
        if (ep.blend)
            x = ep.alpha * x + (1.0f - ep.alpha) * ep.resmat[co];
    } else if (EPI == E_NL) {
        x += ep.bias[n];
        const float c2 = ep.cmat[co];
        x = ep.alpha * (c2 + 0.1f * x) + (1.0f - ep.alpha) * ep.resmat[co];
    }
}

template <int EPI>
__global__ void __launch_bounds__(512, 1) gemm_mma(
    const float* __restrict__ A, int lda,
    const float* __restrict__ W, int ldb,
    float* __restrict__ C, int ldc, int K, Epi ep)
{
    extern __shared__ __align__(16) char dyns[];
    const uint32_t sbase = smem_u32(dyns);

    const int tid  = threadIdx.x;
    const int wid  = tid >> 5, lane = tid & 31;
    const int m0   = blockIdx.y * 256;
    const int n0   = blockIdx.x * 128;
    const int wm   = (wid >> 2) * 64;     // warp m offset (0..192)
    const int wn   = (wid & 3) * 32;      // warp n offset (0..96)

    const int iters = K / BK;

    // cp.async mapping: A 256 rows x 8 chunks, B 128 rows x 8 chunks (16B each)
    const int crow = tid >> 3;            // 0..63
    const int ccol = (tid & 7) * 16;      // byte col
    const int gcol = (tid & 7) * 4;       // fp32 element col

    auto load_stage = [&](int s, int it) {
        const int ko = it * BK;
        const uint32_t smA = sbase + (uint32_t)s * STAGE_BYTES;
        const uint32_t smB = smA + OP_A;
        const float* ga = A + (size_t)(m0 + crow) * lda + ko + gcol;
        const float* gb = W + (size_t)(n0 + crow) * ldb + ko + gcol;
#pragma unroll
        for (int i = 0; i < 4; i++)
            CP_ASYNC16(smA + (uint32_t)(crow + i * 64) * ROWB + ccol, ga + (size_t)(i * 64) * lda);
#pragma unroll
        for (int i = 0; i < 2; i++)
            CP_ASYNC16(smB + (uint32_t)(crow + i * 64) * ROWB + ccol, gb + (size_t)(i * 64) * ldb);
        CP_COMMIT();
    };

    float acc[4][4][4];
#pragma unroll
    for (int i = 0; i < 4; i++)
#pragma unroll
        for (int j = 0; j < 4; j++)
#pragma unroll
            for (int q = 0; q < 4; q++) acc[i][j][q] = 0.0f;

    load_stage(0, 0);
    load_stage(1, 1);

    const int lr = lane & 15, lc = lane >> 4;   // ldmatrix row / 16B-chunk select

    for (int it = 0; it < iters; ++it) {
        CP_WAIT1();
        __syncthreads();
        if (it + 2 < iters) load_stage((it + 2) % NSTG, it + 2);

        const uint32_t smA = sbase + (uint32_t)(it % NSTG) * STAGE_BYTES;
        const uint32_t smB = smA + OP_A;

#pragma unroll
        for (int ks = 0; ks < 4; ks++) {          // 4 x k8 per BK=32
            uint32_t a[4][4], b[2][4];
#pragma unroll
            for (int mt = 0; mt < 4; mt++) {
                LDSM_X4(a[mt], smA + (uint32_t)(wm + mt * 16 + lr) * ROWB + ks * 32 + lc * 16);
#pragma unroll
                for (int q = 0; q < 4; q++) CVT_TF32(a[mt][q]);   // activations -> RNA tf32
            }
#pragma unroll
            for (int bt = 0; bt < 2; bt++)
                LDSM_X4(b[bt], smB + (uint32_t)(wn + bt * 16 + lr) * ROWB + ks * 32 + lc * 16);
#pragma unroll
            for (int mt = 0; mt < 4; mt++)
#pragma unroll
                for (int nt = 0; nt < 4; nt++)
                    MMA_TF32(acc[mt][nt], a[mt], b[nt >> 1][nt & 1], b[nt >> 1][(nt & 1) + 2]);
        }
    }

    // ---------------- epilogue (fused) ----------------
    const int gid = lane >> 2, t4 = lane & 3;
#pragma unroll
    for (int mt = 0; mt < 4; mt++) {
#pragma unroll
        for (int half = 0; half < 2; half++) {
            const int m = m0 + wm + mt * 16 + gid + half * 8;
#pragma unroll
            for (int nt = 0; nt < 4; nt++) {
                const int n = n0 + wn + nt * 8 + t4 * 2;
                const size_t co = (size_t)m * ldc + n;
                float x0 = acc[mt][nt][half * 2];
                float x1 = acc[mt][nt][half * 2 + 1];
                epi_apply<EPI>(x0, n, co, ep);
                epi_apply<EPI>(x1, n + 1, co + 1, ep);
                *(float2*)&C[co] = make_float2(x0, x1);
            }
        }
    }
}

// ---------------- LayerNorm(768) + exact gelu, in place -------------------------
__global__ void ln_gelu_k(float* __restrict__ h,
                          const float* __restrict__ w,
                          const float* __restrict__ b)
{
    const int row = blockIdx.x;
    float* hr = h + (size_t)row * 768;
    const int t = threadIdx.x;

    const float v0 = hr[t], v1 = hr[t + 256], v2 = hr[t + 512];
    float s  = v0 + v1 + v2;
    float ss = v0 * v0 + v1 * v1 + v2 * v2;
#pragma unroll
    for (int o = 16; o > 0; o >>= 1) {
        s  += __shfl_down_sync(0xffffffffu, s, o);
        ss += __shfl_down_sync(0xffffffffu, ss, o);
    }
    __shared__ float rs[8], rss[8], mu_s, rstd_s;
    const int lane = t & 31, wp = t >> 5;
    if (lane == 0) { rs[wp] = s; rss[wp] = ss; }
    __syncthreads();
    if (t == 0) {
        float S = 0.0f, SS = 0.0f;
#pragma unroll
        for (int k = 0; k < 8; k++) { S += rs[k]; SS += rss[k]; }
        const float mu = S * (1.0f / 768.0f);
        mu_s = mu;
        rstd_s = rsqrtf(SS * (1.0f / 768.0f) - mu * mu + 1e-5f);
    }
    __syncthreads();
    const float mu = mu_s, rstd = rstd_s;

#pragma unroll
    for (int k = 0; k < 3; k++) {
        const int c = t + k * 256;
        float x = (((k == 0) ? v0 : (k == 1) ? v1 : v2) - mu) * rstd * w[c] + b[c];
        hr[c] = 0.5f * x * (1.0f + erff(x * 0.70710678118654752f));
    }
}

// ---------------- row L2-normalize(256) + tanh ----------------------------------
__global__ void norm_tanh_k(const float* __restrict__ in, float* __restrict__ out)
{
    const int wp = threadIdx.x >> 5, lane = threadIdx.x & 31;
    const size_t row = (size_t)blockIdx.x * 8 + wp;
    const float* r = in + row * QD;
    const float4 a = *(const float4*)(r + lane * 4);
    const float4 c = *(const float4*)(r + 128 + lane * 4);
    float s = a.x * a.x + a.y * a.y + a.z * a.z + a.w * a.w
            + c.x * c.x + c.y * c.y + c.z * c.z + c.w * c.w;
#pragma unroll
    for (int o = 16; o > 0; o >>= 1) s += __shfl_xor_sync(0xffffffffu, s, o);
    const float inv = 1.0f / (sqrtf(s) + 1e-8f);

    float* o = out + row * QD;
    *(float4*)(o + lane * 4) =
        make_float4(tanhf(a.x * inv), tanhf(a.y * inv), tanhf(a.z * inv), tanhf(a.w * inv));
    *(float4*)(o + 128 + lane * 4) =
        make_float4(tanhf(c.x * inv), tanhf(c.y * inv), tanhf(c.z * inv), tanhf(c.w * inv));
}

// ---------------- merged weight transpose + tf32 rounding -----------------------
// Each entry converts one [K,N] fp32 matrix (+coloff) into [N,K] tf32-rounded fp32.
struct ConvEnt { const float* src; int dstoff; int K; int ldsrc; int coloff; int dotanh; int blk0; };
struct ConvTab { ConvEnt e[32]; int n; };

__global__ void conv_all_k(ConvTab tab, float* __restrict__ dst)
{
    const int blk = blockIdx.x;
    int lo = 0;
    for (int i = 0; i < tab.n; i++)
        if (tab.e[i].blk0 <= blk) lo = i;
    const ConvEnt& E = tab.e[lo];
    const int le = (blk - E.blk0) * 256 + threadIdx.x;   // local element
    const int n = le / E.K, k = le - n * E.K;
    float v = E.src[(size_t)k * E.ldsrc + E.coloff + n];
    if (E.dotanh) v = tanhf(v);
    dst[E.dstoff + (size_t)n * E.K + k] = tf32r(v);
}

__global__ void prep_k(const float* __restrict__ gp, float* __restrict__ lin,
                       float* __restrict__ p3, float* __restrict__ p4,
                       float* __restrict__ p5)
{
    const int i = blockIdx.x * 256 + threadIdx.x;
    if (i < 8 * QD) {
        const float* p = gp + (size_t)i * 6;
        lin[i] = sinf(p[0]) + cosf(p[1]) + tanhf(p[2]);
        p3[i] = p[3]; p4[i] = p[4]; p5[i] = p[5];
    }
}

// ---------------- host ----------------------------------------------------------
static void launch_gemm(int epi, const float* A, int lda,
                        const float* W, int K, int N,
                        float* C, int ldc, const Epi& ep)
{
    dim3 grid(N / 128, BATCH_N / 256);
    dim3 blk(512);
    switch (epi) {
        case E_BIAS: gemm_mma<E_BIAS><<<grid, blk, SMEM_DYN>>>(A, lda, W, K, C, ldc, K, ep); break;
        case E_SILU: gemm_mma<E_SILU><<<grid, blk, SMEM_DYN>>>(A, lda, W, K, C, ldc, K, ep); break;
        case E_TANH: gemm_mma<E_TANH><<<grid, blk, SMEM_DYN>>>(A, lda, W, K, C, ldc, K, ep); break;
        case E_GATE: gemm_mma<E_GATE><<<grid, blk, SMEM_DYN>>>(A, lda, W, K, C, ldc, K, ep); break;
        case E_NL:   gemm_mma<E_NL>  <<<grid, blk, SMEM_DYN>>>(A, lda, W, K, C, ldc, K, ep); break;
    }
}

// tf32 weight-buffer fp32-element offsets
#define W01T 0
#define W02T 589824
#define W11T 1179648
#define W12T 1572864
#define WVT  1966080
#define WOT  2097152
#define TENT 2228224
#define NW1T 2752512
#define NW2T 3014656

extern "C" void kernel_launch(void* const* d_in, const int* in_sizes, int n_in,
                              void* d_out, int out_size)
{
    (void)in_sizes; (void)n_in; (void)out_size;
    const float* x    = (const float*)d_in[0];
    const float* w01  = (const float*)d_in[1];
    const float* b01  = (const float*)d_in[2];
    const float* lnw  = (const float*)d_in[3];
    const float* lnb  = (const float*)d_in[4];
    const float* w02  = (const float*)d_in[5];
    const float* b02  = (const float*)d_in[6];
    const float* w11  = (const float*)d_in[7];
    const float* b11  = (const float*)d_in[8];
    const float* w12  = (const float*)d_in[9];
    const float* b12  = (const float*)d_in[10];
    const float* wqkv = (const float*)d_in[11];
    const float* bqkv = (const float*)d_in[12];
    const float* wo   = (const float*)d_in[13];
    const float* bo   = (const float*)d_in[14];
    const float* gp   = (const float*)d_in[15];
    const float* ent  = (const float*)d_in[16];
    const float* nw1  = (const float*)d_in[17];
    const float* nb1  = (const float*)d_in[18];
    const float* nw2  = (const float*)d_in[19];
    const float* nb2  = (const float*)d_in[20];

    cudaFuncSetAttribute(gemm_mma<E_BIAS>, cudaFuncAttributeMaxDynamicSharedMemorySize, SMEM_DYN);
    cudaFuncSetAttribute(gemm_mma<E_SILU>, cudaFuncAttributeMaxDynamicSharedMemorySize, SMEM_DYN);
    cudaFuncSetAttribute(gemm_mma<E_TANH>, cudaFuncAttributeMaxDynamicSharedMemorySize, SMEM_DYN);
    cudaFuncSetAttribute(gemm_mma<E_GATE>, cudaFuncAttributeMaxDynamicSharedMemorySize, SMEM_DYN);
    cudaFuncSetAttribute(gemm_mma<E_NL>,   cudaFuncAttributeMaxDynamicSharedMemorySize, SMEM_DYN);

    float *H, *FB, *GATEB, *WT;
    cudaGetSymbolAddress((void**)&H,     g_h);
    cudaGetSymbolAddress((void**)&FB,    g_f);
    cudaGetSymbolAddress((void**)&WT,    g_wtf);
    cudaGetSymbolAddress((void**)&GATEB, g_gate);

    float* F[3];
    for (int k = 0; k < 3; k++) F[k] = FB + (size_t)k * BATCH_N * QD;
    float* LIN = GATEB + 0 * 8 * QD;
    float* P3  = GATEB + 1 * 8 * QD;
    float* P4  = GATEB + 2 * 8 * QD;
    float* P5  = GATEB + 3 * 8 * QD;

    // ---- merged one-time weight transpose/round (single launch) ----
    {
        ConvTab tab; int ne = 0, blk = 0;
        auto add = [&](const float* src, size_t zs, int ldsrc, int coloff,
                       int dstoff, size_t dzs, int K, int N, int th, int zn) {
            for (int z = 0; z < zn; z++) {
                tab.e[ne] = { src + (size_t)z * zs, (int)(dstoff + (size_t)z * dzs),
                              K, ldsrc, coloff, th, blk };
                blk += (K * N) / 256;
                ne++;
            }
        };
        add(w01, (size_t)QD * 768, 768, 0,   W01T, 196608, QD, 768, 0, 3);
        add(w02, (size_t)768 * QD, QD,  0,   W02T, 196608, 768, QD, 0, 3);
        add(w11, (size_t)QD * 512, 512, 0,   W11T, 131072, QD, 512, 0, 3);
        add(w12, (size_t)512 * QD, QD,  0,   W12T, 131072, 512, QD, 0, 3);
        add(wqkv, (size_t)QD * 768, 768, 512, WVT, 65536, QD, QD, 0, 2);
        add(wo,  (size_t)QD * QD,  QD,  0,   WOT,  65536, QD, QD, 0, 2);
        add(ent, (size_t)QD * QD,  QD,  0,   TENT, 65536, QD, QD, 1, 8);
        add(nw1, (size_t)QD * QD,  QD,  0,   NW1T, 65536, QD, QD, 0, 4);
        add(nw2, (size_t)QD * QD,  QD,  0,   NW2T, 65536, QD, QD, 0, 4);
        tab.n = ne;
        conv_all_k<<<blk, 256>>>(tab, WT);
    }
    prep_k<<<8, 256>>>(gp, LIN, P3, P4, P5);

    const float* cur = x;
    int scur = -1;

    for (int li = 0; li < 8; li++) {
        int s0 = -1, s1 = -1;
        for (int k = 0; k < 3; k++)
            if (k != scur) { if (s0 < 0) s0 = k; else if (s1 < 0) s1 = k; }
        float* F0 = F[s0]; float* F1 = F[s1];

        const int t = li % 3;
        const int odd = li & 1;
        const float alpha = (li < 4) ? 0.8f : 0.6f;

        if (t == 0) {
            const int i = li / 3;
            Epi e = {}; e.bias = b01 + i * 768;
            launch_gemm(E_BIAS, cur, QD, WT + W01T + (size_t)i * 196608, QD, 768, H, 768, e);
            ln_gelu_k<<<BATCH_N, 256>>>(H, lnw + i * 768, lnb + i * 768);
            Epi e2 = {}; e2.bias = b02 + i * QD;
            launch_gemm(E_BIAS, H, 768, WT + W02T + (size_t)i * 196608, 768, QD, F0, QD, e2);
        } else if (t == 1) {
            const int i = (li - 1) / 3;
            Epi e = {}; e.bias = b11 + i * 512;
            launch_gemm(E_SILU, cur, QD, WT + W11T + (size_t)i * 131072, QD, 512, H, 512, e);
            Epi e2 = {}; e2.bias = b12 + i * QD;
            launch_gemm(E_BIAS, H, 512, WT + W12T + (size_t)i * 131072, 512, QD, F0, QD, e2);
        } else {
            const int i = (li - 2) / 3;
            Epi e = {}; e.bias = bqkv + i * 768 + 512;
            launch_gemm(E_BIAS, cur, QD, WT + WVT + (size_t)i * 65536, QD, QD, F1, QD, e);
            Epi e2 = {}; e2.bias = bo + i * QD;
            launch_gemm(E_BIAS, F1, QD, WT + WOT + (size_t)i * 65536, QD, QD, F0, QD, e2);
        }

        // entangle + gate (+ blend on even layers)
        Epi eg = {};
        eg.cmat = F0; eg.resmat = cur;
        eg.lin = LIN + li * QD; eg.p3 = P3 + li * QD;
        eg.p4 = P4 + li * QD;   eg.p5 = P5 + li * QD;
        eg.alpha = alpha; eg.blend = !odd;
        launch_gemm(E_GATE, F0, QD, WT + TENT + (size_t)li * 65536, QD, QD, F1, QD, eg);

        if (odd) {
            const int j = li / 2;
            Epi et = {}; et.bias = nb1 + j * QD;
            launch_gemm(E_TANH, F1, QD, WT + NW1T + (size_t)j * 65536, QD, QD, H, QD, et);
            Epi en = {}; en.bias = nb2 + j * QD;
            en.cmat = F1; en.resmat = cur; en.alpha = alpha;
            launch_gemm(E_NL, H, QD, WT + NW2T + (size_t)j * 65536, QD, QD, F1, QD, en);
        }

        if (li == 7) {
            norm_tanh_k<<<BATCH_N / 8, 256>>>(F1, (float*)d_out);
            cur = (float*)d_out;
        } else {
            norm_tanh_k<<<BATCH_N / 8, 256>>>(F1, F1);
            cur = F1; scur = s1;
        }
    }
}

// round 7
// speedup vs baseline: 3.6647x; 1.0294x over previous
#include <cuda_runtime.h>
#include <cuda_bf16.h>
#include <math.h>
#include <stdint.h>
#include <stddef.h>

#define BATCH_N 65536
#define QD      256

// ---------------- ptx helpers ---------------------------------------------------
__device__ __forceinline__ uint32_t smem_u32(const void* p) {
    uint32_t a;
    asm("{ .reg .u64 t; cvta.to.shared.u64 t, %1; cvt.u32.u64 %0, t; }" : "=r"(a) : "l"(p));
    return a;
}

#define CP_ASYNC16(dst, src) \
    asm volatile("cp.async.cg.shared.global [%0], [%1], 16;" :: "r"(dst), "l"(src) : "memory")
#define CP_COMMIT() asm volatile("cp.async.commit_group;" ::: "memory")
#define CP_WAIT1()  asm volatile("cp.async.wait_group 1;" ::: "memory")
#define CP_WAIT0()  asm volatile("cp.async.wait_group 0;" ::: "memory")

#define LDSM_X4(r, addr) \
    asm volatile("ldmatrix.sync.aligned.m8n8.x4.shared.b16 {%0,%1,%2,%3}, [%4];" \
        : "=r"((r)[0]), "=r"((r)[1]), "=r"((r)[2]), "=r"((r)[3]) : "r"(addr))

#define MMA_TF32(c, a, b0, b1) \
    asm volatile("mma.sync.aligned.m16n8k8.row.col.f32.tf32.tf32.f32 " \
        "{%0,%1,%2,%3}, {%4,%5,%6,%7}, {%8,%9}, {%0,%1,%2,%3};" \
        : "+f"((c)[0]), "+f"((c)[1]), "+f"((c)[2]), "+f"((c)[3]) \
        : "r"((a)[0]), "r"((a)[1]), "r"((a)[2]), "r"((a)[3]), "r"(b0), "r"(b1))

#define CVT_TF32(r) asm volatile("cvt.rna.tf32.f32 %0, %0;" : "+r"(r))

__device__ __forceinline__ float tf32r(float v) {
    asm("cvt.rna.tf32.f32 %0, %0;" : "+f"(v));
    return v;
}

// ---------------- scratch -------------------------------------------------------
static __device__ __align__(16) float g_h[(size_t)BATCH_N * 768];
static __device__ __align__(16) float g_f[3][(size_t)BATCH_N * QD];
static __device__ __align__(16) float g_wtf[3276800];
static __device__ __align__(16) float g_gate[4][8 * QD];

struct Epi {
    const float* bias;
    const float* cmat;
    const float* resmat;
    const float* lin; const float* p3; const float* p4; const float* p5;
    float alpha;
    int   blend;
};

enum { E_BIAS = 0, E_SILU = 1, E_TANH = 2, E_GATE = 3, E_NL = 4 };

#define ROWB 144                       // 128B data + 16B skew

template <int EPI>
__device__ __forceinline__ void epi_apply(float& x, int n, size_t co, const Epi& ep) {
    if (EPI == E_BIAS) {
        x += ep.bias[n];
    } else if (EPI == E_SILU) {
        x += ep.bias[n];
        x = x / (1.0f + __expf(-x));
    } else if (EPI == E_TANH) {
        x += ep.bias[n];
        x = tanhf(x);
    } else if (EPI == E_GATE) {
        const float c = ep.cmat[co];
        const float g = (ep.lin[n] * c
                         + 0.5f * __sinf(ep.p3[n] * c + ep.p4[n])
                         + 0.5f * __cosf(ep.p5[n] * c)) * 0.25f;
        x = (c + 0.3f * g + 0.2f * x) * (1.0f / 1.5f);
        if (ep.blend)
            x = ep.alpha * x + (1.0f - ep.alpha) * ep.resmat[co];
    } else if (EPI == E_NL) {
        x += ep.bias[n];
        const float c2 = ep.cmat[co];
        x = ep.alpha * (c2 + 0.1f * x) + (1.0f - ep.alpha) * ep.resmat[co];
    }
}

// ============ wide GEMM: CTA 256x128, 512 thr, warp 64x32 (N=768/512) ===========
#define OP_A  (256 * ROWB)
#define OP_Bw (128 * ROWB)
#define STGW  (OP_A + OP_Bw)
#define NSTG  3
#define SMEM_DYN (NSTG * STGW)         // 165888

template <int EPI>
__global__ void __launch_bounds__(512, 1) gemm_wide(
    const float* __restrict__ A, int lda,
    const float* __restrict__ W, int ldb,
    float* __restrict__ C, int ldc, int K, Epi ep)
{
    extern __shared__ __align__(16) char dyns[];
    const uint32_t sbase = smem_u32(dyns);

    const int tid  = threadIdx.x;
    const int wid  = tid >> 5, lane = tid & 31;
    const int m0   = blockIdx.y * 256;
    const int n0   = blockIdx.x * 128;
    const int wm   = (wid >> 2) * 64;
    const int wn   = (wid & 3) * 32;

    const int iters = K / 32;

    const int crow = tid >> 3;
    const int ccol = (tid & 7) * 16;
    const int gcol = (tid & 7) * 4;

    auto load_stage = [&](int s, int it) {
        const int ko = it * 32;
        const uint32_t smA = sbase + (uint32_t)s * STGW;
        const uint32_t smB = smA + OP_A;
        const float* ga = A + (size_t)(m0 + crow) * lda + ko + gcol;
        const float* gb = W + (size_t)(n0 + crow) * ldb + ko + gcol;
#pragma unroll
        for (int i = 0; i < 4; i++)
            CP_ASYNC16(smA + (uint32_t)(crow + i * 64) * ROWB + ccol, ga + (size_t)(i * 64) * lda);
#pragma unroll
        for (int i = 0; i < 2; i++)
            CP_ASYNC16(smB + (uint32_t)(crow + i * 64) * ROWB + ccol, gb + (size_t)(i * 64) * ldb);
        CP_COMMIT();
    };

    float acc[4][4][4];
#pragma unroll
    for (int i = 0; i < 4; i++)
#pragma unroll
        for (int j = 0; j < 4; j++)
#pragma unroll
            for (int q = 0; q < 4; q++) acc[i][j][q] = 0.0f;

    load_stage(0, 0);
    load_stage(1, 1);

    const int lr = lane & 15, lc = lane >> 4;

    for (int it = 0; it < iters; ++it) {
        if (it == iters - 1) { CP_WAIT0(); } else { CP_WAIT1(); }
        __syncthreads();
        if (it + 2 < iters) load_stage((it + 2) % NSTG, it + 2);

        const uint32_t smA = sbase + (uint32_t)(it % NSTG) * STGW;
        const uint32_t smB = smA + OP_A;

#pragma unroll
        for (int ks = 0; ks < 4; ks++) {
            uint32_t a[4][4], b[2][4];
#pragma unroll
            for (int mt = 0; mt < 4; mt++) {
                LDSM_X4(a[mt], smA + (uint32_t)(wm + mt * 16 + lr) * ROWB + ks * 32 + lc * 16);
#pragma unroll
                for (int q = 0; q < 4; q++) CVT_TF32(a[mt][q]);
            }
#pragma unroll
            for (int bt = 0; bt < 2; bt++)
                LDSM_X4(b[bt], smB + (uint32_t)(wn + bt * 16 + lr) * ROWB + ks * 32 + lc * 16);
#pragma unroll
            for (int mt = 0; mt < 4; mt++)
#pragma unroll
                for (int nt = 0; nt < 4; nt++)
                    MMA_TF32(acc[mt][nt], a[mt], b[nt >> 1][nt & 1], b[nt >> 1][(nt & 1) + 2]);
        }
    }

    const int gid = lane >> 2, t4 = lane & 3;
#pragma unroll
    for (int mt = 0; mt < 4; mt++) {
#pragma unroll
        for (int half = 0; half < 2; half++) {
            const int m = m0 + wm + mt * 16 + gid + half * 8;
#pragma unroll
            for (int nt = 0; nt < 4; nt++) {
                const int n = n0 + wn + nt * 8 + t4 * 2;
                const size_t co = (size_t)m * ldc + n;
                float x0 = acc[mt][nt][half * 2];
                float x1 = acc[mt][nt][half * 2 + 1];
                epi_apply<EPI>(x0, n, co, ep);
                epi_apply<EPI>(x1, n + 1, co + 1, ep);
                *(float2*)&C[co] = make_float2(x0, x1);
            }
        }
    }
}

// ============ n256 GEMM: CTA 128x256, 256 thr, warp 64x64, optional row-norm ====
#define OP_An (128 * ROWB)
#define OP_Bn (256 * ROWB)
#define STGN  (OP_An + OP_Bn)          // same 55296 -> 3*=165888
#define SV_STRIDE 260

template <int EPI, int NORM>
__global__ void __launch_bounds__(256, 1) gemm_n256(
    const float* __restrict__ A, int lda,
    const float* __restrict__ W, int ldb,
    float* __restrict__ C, int K, Epi ep)
{
    extern __shared__ __align__(16) char dyns[];
    const uint32_t sbase = smem_u32(dyns);

    const int tid  = threadIdx.x;
    const int wid  = tid >> 5, lane = tid & 31;
    const int m0   = blockIdx.x * 128;
    const int wm   = (wid >> 2) * 64;      // 0 / 64
    const int wn   = (wid & 3) * 64;       // 0..192

    const int iters = K / 32;

    const int crow = tid >> 3;             // 0..31
    const int ccol = (tid & 7) * 16;
    const int gcol = (tid & 7) * 4;

    auto load_stage = [&](int s, int it) {
        const int ko = it * 32;
        const uint32_t smA = sbase + (uint32_t)s * STGN;
        const uint32_t smB = smA + OP_An;
        const float* ga = A + (size_t)(m0 + crow) * lda + ko + gcol;
        const float* gb = W + (size_t)crow * ldb + ko + gcol;
#pragma unroll
        for (int i = 0; i < 4; i++)
            CP_ASYNC16(smA + (uint32_t)(crow + i * 32) * ROWB + ccol, ga + (size_t)(i * 32) * lda);
#pragma unroll
        for (int i = 0; i < 8; i++)
            CP_ASYNC16(smB + (uint32_t)(crow + i * 32) * ROWB + ccol, gb + (size_t)(i * 32) * ldb);
        CP_COMMIT();
    };

    float acc[4][8][4];
#pragma unroll
    for (int i = 0; i < 4; i++)
#pragma unroll
        for (int j = 0; j < 8; j++)
#pragma unroll
            for (int q = 0; q < 4; q++) acc[i][j][q] = 0.0f;

    load_stage(0, 0);
    load_stage(1, 1);

    const int lr = lane & 15, lc = lane >> 4;

    for (int it = 0; it < iters; ++it) {
        if (it == iters - 1) { CP_WAIT0(); } else { CP_WAIT1(); }
        __syncthreads();
        if (it + 2 < iters) load_stage((it + 2) % NSTG, it + 2);

        const uint32_t smA = sbase + (uint32_t)(it % NSTG) * STGN;
        const uint32_t smB = smA + OP_An;

#pragma unroll
        for (int ks = 0; ks < 4; ks++) {
            uint32_t a[4][4], b[4][4];
#pragma unroll
            for (int mt = 0; mt < 4; mt++) {
                LDSM_X4(a[mt], smA + (uint32_t)(wm + mt * 16 + lr) * ROWB + ks * 32 + lc * 16);
#pragma unroll
                for (int q = 0; q < 4; q++) CVT_TF32(a[mt][q]);
            }
#pragma unroll
            for (int bt = 0; bt < 4; bt++)
                LDSM_X4(b[bt], smB + (uint32_t)(wn + bt * 16 + lr) * ROWB + ks * 32 + lc * 16);
#pragma unroll
            for (int mt = 0; mt < 4; mt++)
#pragma unroll
                for (int nt = 0; nt < 8; nt++)
                    MMA_TF32(acc[mt][nt], a[mt], b[nt >> 1][nt & 1], b[nt >> 1][(nt & 1) + 2]);
        }
    }

    const int gid = lane >> 2, t4 = lane & 3;

    if (!NORM) {
#pragma unroll
        for (int mt = 0; mt < 4; mt++) {
#pragma unroll
            for (int half = 0; half < 2; half++) {
                const int m = m0 + wm + mt * 16 + gid + half * 8;
#pragma unroll
                for (int nt = 0; nt < 8; nt++) {
                    const int n = wn + nt * 8 + t4 * 2;
                    const size_t co = (size_t)m * QD + n;
                    float x0 = acc[mt][nt][half * 2];
                    float x1 = acc[mt][nt][half * 2 + 1];
                    epi_apply<EPI>(x0, n, co, ep);
                    epi_apply<EPI>(x1, n + 1, co + 1, ep);
                    *(float2*)&C[co] = make_float2(x0, x1);
                }
            }
        }
    } else {
        // stage epi-applied values into (now dead) pipeline smem, row-norm, tanh
        float* sv = (float*)dyns;
        __syncthreads();   // all ldmatrix reads done before overwrite
#pragma unroll
        for (int mt = 0; mt < 4; mt++) {
#pragma unroll
            for (int half = 0; half < 2; half++) {
                const int ml = wm + mt * 16 + gid + half * 8;   // 0..127 local row
                const int m  = m0 + ml;
#pragma unroll
                for (int nt = 0; nt < 8; nt++) {
                    const int n = wn + nt * 8 + t4 * 2;
                    const size_t co = (size_t)m * QD + n;
                    float x0 = acc[mt][nt][half * 2];
                    float x1 = acc[mt][nt][half * 2 + 1];
                    epi_apply<EPI>(x0, n, co, ep);
                    epi_apply<EPI>(x1, n + 1, co + 1, ep);
                    *(float2*)&sv[ml * SV_STRIDE + n] = make_float2(x0, x1);
                }
            }
        }
        __syncthreads();
        if (tid < 128) {
            const float* r = &sv[tid * SV_STRIDE];
            float s = 0.0f;
#pragma unroll 16
            for (int c = 0; c < 256; c += 4) {
                const float4 v = *(const float4*)&r[c];
                s += v.x * v.x + v.y * v.y + v.z * v.z + v.w * v.w;
            }
            sv[tid * SV_STRIDE + 256] = 1.0f / (sqrtf(s) + 1e-8f);
        }
        __syncthreads();
#pragma unroll 1
        for (int i = 0; i < 32; i++) {
            const int idx = i * 1024 + tid * 4;
            const int row = idx >> 8, col = idx & 255;
            const float inv = sv[row * SV_STRIDE + 256];
            const float4 v = *(const float4*)&sv[row * SV_STRIDE + col];
            *(float4*)&C[(size_t)(m0 + row) * QD + col] =
                make_float4(tanhf(v.x * inv), tanhf(v.y * inv),
                            tanhf(v.z * inv), tanhf(v.w * inv));
        }
    }
}

// ---------------- LayerNorm(768) + exact gelu, in place -------------------------
__global__ void ln_gelu_k(float* __restrict__ h,
                          const float* __restrict__ w,
                          const float* __restrict__ b)
{
    const int row = blockIdx.x;
    float* hr = h + (size_t)row * 768;
    const int t = threadIdx.x;

    const float v0 = hr[t], v1 = hr[t + 256], v2 = hr[t + 512];
    float s  = v0 + v1 + v2;
    float ss = v0 * v0 + v1 * v1 + v2 * v2;
#pragma unroll
    for (int o = 16; o > 0; o >>= 1) {
        s  += __shfl_down_sync(0xffffffffu, s, o);
        ss += __shfl_down_sync(0xffffffffu, ss, o);
    }
    __shared__ float rs[8], rss[8], mu_s, rstd_s;
    const int lane = t & 31, wp = t >> 5;
    if (lane == 0) { rs[wp] = s; rss[wp] = ss; }
    __syncthreads();
    if (t == 0) {
        float S = 0.0f, SS = 0.0f;
#pragma unroll
        for (int k = 0; k < 8; k++) { S += rs[k]; SS += rss[k]; }
        const float mu = S * (1.0f / 768.0f);
        mu_s = mu;
        rstd_s = rsqrtf(SS * (1.0f / 768.0f) - mu * mu + 1e-5f);
    }
    __syncthreads();
    const float mu = mu_s, rstd = rstd_s;

#pragma unroll
    for (int k = 0; k < 3; k++) {
        const int c = t + k * 256;
        float x = (((k == 0) ? v0 : (k == 1) ? v1 : v2) - mu) * rstd * w[c] + b[c];
        hr[c] = 0.5f * x * (1.0f + erff(x * 0.70710678118654752f));
    }
}

// ---------------- merged weight transpose + tf32 rounding -----------------------
struct ConvEnt { const float* src; int dstoff; int K; int ldsrc; int coloff; int dotanh; int blk0; };
struct ConvTab { ConvEnt e[32]; int n; };

__global__ void conv_all_k(ConvTab tab, float* __restrict__ dst)
{
    const int blk = blockIdx.x;
    int lo = 0;
    for (int i = 0; i < tab.n; i++)
        if (tab.e[i].blk0 <= blk) lo = i;
    const ConvEnt& E = tab.e[lo];
    const int le = (blk - E.blk0) * 256 + threadIdx.x;
    const int n = le / E.K, k = le - n * E.K;
    float v = E.src[(size_t)k * E.ldsrc + E.coloff + n];
    if (E.dotanh) v = tanhf(v);
    dst[E.dstoff + (size_t)n * E.K + k] = tf32r(v);
}

__global__ void prep_k(const float* __restrict__ gp, float* __restrict__ lin,
                       float* __restrict__ p3, float* __restrict__ p4,
                       float* __restrict__ p5)
{
    const int i = blockIdx.x * 256 + threadIdx.x;
    if (i < 8 * QD) {
        const float* p = gp + (size_t)i * 6;
        lin[i] = sinf(p[0]) + cosf(p[1]) + tanhf(p[2]);
        p3[i] = p[3]; p4[i] = p[4]; p5[i] = p[5];
    }
}

// ---------------- host ----------------------------------------------------------
static void launch_wide(int epi, const float* A, int lda,
                        const float* W, int K, int N,
                        float* C, int ldc, const Epi& ep)
{
    dim3 grid(N / 128, BATCH_N / 256);
    dim3 blk(512);
    if (epi == E_BIAS) gemm_wide<E_BIAS><<<grid, blk, SMEM_DYN>>>(A, lda, W, K, C, ldc, K, ep);
    else               gemm_wide<E_SILU><<<grid, blk, SMEM_DYN>>>(A, lda, W, K, C, ldc, K, ep);
}

template <int EPI, int NORM>
static void launch_n256(const float* A, int lda, const float* W, int K,
                        float* C, const Epi& ep)
{
    gemm_n256<EPI, NORM><<<BATCH_N / 128, 256, SMEM_DYN>>>(A, lda, W, K, C, K, ep);
}

// tf32 weight-buffer fp32-element offsets
#define W01T 0
#define W02T 589824
#define W11T 1179648
#define W12T 1572864
#define WVT  1966080
#define WOT  2097152
#define TENT 2228224
#define NW1T 2752512
#define NW2T 3014656

extern "C" void kernel_launch(void* const* d_in, const int* in_sizes, int n_in,
                              void* d_out, int out_size)
{
    (void)in_sizes; (void)n_in; (void)out_size;
    const float* x    = (const float*)d_in[0];
    const float* w01  = (const float*)d_in[1];
    const float* b01  = (const float*)d_in[2];
    const float* lnw  = (const float*)d_in[3];
    const float* lnb  = (const float*)d_in[4];
    const float* w02  = (const float*)d_in[5];
    const float* b02  = (const float*)d_in[6];
    const float* w11  = (const float*)d_in[7];
    const float* b11  = (const float*)d_in[8];
    const float* w12  = (const float*)d_in[9];
    const float* b12  = (const float*)d_in[10];
    const float* wqkv = (const float*)d_in[11];
    const float* bqkv = (const float*)d_in[12];
    const float* wo   = (const float*)d_in[13];
    const float* bo   = (const float*)d_in[14];
    const float* gp   = (const float*)d_in[15];
    const float* ent  = (const float*)d_in[16];
    const float* nw1  = (const float*)d_in[17];
    const float* nb1  = (const float*)d_in[18];
    const float* nw2  = (const float*)d_in[19];
    const float* nb2  = (const float*)d_in[20];

    cudaFuncSetAttribute(gemm_wide<E_BIAS>, cudaFuncAttributeMaxDynamicSharedMemorySize, SMEM_DYN);
    cudaFuncSetAttribute(gemm_wide<E_SILU>, cudaFuncAttributeMaxDynamicSharedMemorySize, SMEM_DYN);
    cudaFuncSetAttribute(gemm_n256<E_BIAS, 0>, cudaFuncAttributeMaxDynamicSharedMemorySize, SMEM_DYN);
    cudaFuncSetAttribute(gemm_n256<E_TANH, 0>, cudaFuncAttributeMaxDynamicSharedMemorySize, SMEM_DYN);
    cudaFuncSetAttribute(gemm_n256<E_GATE, 0>, cudaFuncAttributeMaxDynamicSharedMemorySize, SMEM_DYN);
    cudaFuncSetAttribute(gemm_n256<E_GATE, 1>, cudaFuncAttributeMaxDynamicSharedMemorySize, SMEM_DYN);
    cudaFuncSetAttribute(gemm_n256<E_NL, 1>,   cudaFuncAttributeMaxDynamicSharedMemorySize, SMEM_DYN);

    float *H, *FB, *GATEB, *WT;
    cudaGetSymbolAddress((void**)&H,     g_h);
    cudaGetSymbolAddress((void**)&FB,    g_f);
    cudaGetSymbolAddress((void**)&WT,    g_wtf);
    cudaGetSymbolAddress((void**)&GATEB, g_gate);

    float* F[3];
    for (int k = 0; k < 3; k++) F[k] = FB + (size_t)k * BATCH_N * QD;
    float* LIN = GATEB + 0 * 8 * QD;
    float* P3  = GATEB + 1 * 8 * QD;
    float* P4  = GATEB + 2 * 8 * QD;
    float* P5  = GATEB + 3 * 8 * QD;

    // ---- merged one-time weight transpose/round ----
    {
        ConvTab tab; int ne = 0, blk = 0;
        auto add = [&](const float* src, size_t zs, int ldsrc, int coloff,
                       int dstoff, size_t dzs, int K, int N, int th, int zn) {
            for (int z = 0; z < zn; z++) {
                tab.e[ne] = { src + (size_t)z * zs, (int)(dstoff + (size_t)z * dzs),
                              K, ldsrc, coloff, th, blk };
                blk += (K * N) / 256;
                ne++;
            }
        };
        add(w01, (size_t)QD * 768, 768, 0,   W01T, 196608, QD, 768, 0, 3);
        add(w02, (size_t)768 * QD, QD,  0,   W02T, 196608, 768, QD, 0, 3);
        add(w11, (size_t)QD * 512, 512, 0,   W11T, 131072, QD, 512, 0, 3);
        add(w12, (size_t)512 * QD, QD,  0,   W12T, 131072, 512, QD, 0, 3);
        add(wqkv, (size_t)QD * 768, 768, 512, WVT, 65536, QD, QD, 0, 2);
        add(wo,  (size_t)QD * QD,  QD,  0,   WOT,  65536, QD, QD, 0, 2);
        add(ent, (size_t)QD * QD,  QD,  0,   TENT, 65536, QD, QD, 1, 8);
        add(nw1, (size_t)QD * QD,  QD,  0,   NW1T, 65536, QD, QD, 0, 4);
        add(nw2, (size_t)QD * QD,  QD,  0,   NW2T, 65536, QD, QD, 0, 4);
        tab.n = ne;
        conv_all_k<<<blk, 256>>>(tab, WT);
    }
    prep_k<<<8, 256>>>(gp, LIN, P3, P4, P5);

    const float* cur = x;
    int scur = -1;

    for (int li = 0; li < 8; li++) {
        int s0 = -1, s1 = -1;
        for (int k = 0; k < 3; k++)
            if (k != scur) { if (s0 < 0) s0 = k; else if (s1 < 0) s1 = k; }
        float* F0 = F[s0]; float* F1 = F[s1];

        const int t = li % 3;
        const int odd = li & 1;
        const float alpha = (li < 4) ? 0.8f : 0.6f;

        if (t == 0) {
            const int i = li / 3;
            Epi e = {}; e.bias = b01 + i * 768;
            launch_wide(E_BIAS, cur, QD, WT + W01T + (size_t)i * 196608, QD, 768, H, 768, e);
            ln_gelu_k<<<BATCH_N, 256>>>(H, lnw + i * 768, lnb + i * 768);
            Epi e2 = {}; e2.bias = b02 + i * QD;
            launch_n256<E_BIAS, 0>(H, 768, WT + W02T + (size_t)i * 196608, 768, F0, e2);
        } else if (t == 1) {
            const int i = (li - 1) / 3;
            Epi e = {}; e.bias = b11 + i * 512;
            launch_wide(E_SILU, cur, QD, WT + W11T + (size_t)i * 131072, QD, 512, H, 512, e);
            Epi e2 = {}; e2.bias = b12 + i * QD;
            launch_n256<E_BIAS, 0>(H, 512, WT + W12T + (size_t)i * 131072, 512, F0, e2);
        } else {
            const int i = (li - 2) / 3;
            Epi e = {}; e.bias = bqkv + i * 768 + 512;
            launch_n256<E_BIAS, 0>(cur, QD, WT + WVT + (size_t)i * 65536, QD, F1, e);
            Epi e2 = {}; e2.bias = bo + i * QD;
            launch_n256<E_BIAS, 0>(F1, QD, WT + WOT + (size_t)i * 65536, QD, F0, e2);
        }

        // entangle + gate; even layers also blend + row-norm + tanh (final for layer)
        Epi eg = {};
        eg.cmat = F0; eg.resmat = cur;
        eg.lin = LIN + li * QD; eg.p3 = P3 + li * QD;
        eg.p4 = P4 + li * QD;   eg.p5 = P5 + li * QD;
        eg.alpha = alpha; eg.blend = !odd;
        if (!odd) {
            launch_n256<E_GATE, 1>(F0, QD, WT + TENT + (size_t)li * 65536, QD, F1, eg);
            cur = F1; scur = s1;
        } else {
            launch_n256<E_GATE, 0>(F0, QD, WT + TENT + (size_t)li * 65536, QD, F1, eg);
            const int j = li / 2;
            Epi et = {}; et.bias = nb1 + j * QD;
            launch_n256<E_TANH, 0>(F1, QD, WT + NW1T + (size_t)j * 65536, QD, H, et);
            Epi en = {}; en.bias = nb2 + j * QD;
            en.cmat = F1; en.resmat = cur; en.alpha = alpha;
            float* dst = (li == 7) ? (float*)d_out : F1;
            launch_n256<E_NL, 1>(H, QD, WT + NW2T + (size_t)j * 65536, QD, dst, en);
            cur = dst; scur = s1;
        }
    }
}